// round 1
// baseline (speedup 1.0000x reference)
#include <cuda_runtime.h>

// ---------------------------------------------------------------------------
// LocalTransformerBlock: LN1 -> QKV -> block-local attention -> O-proj(+res)
//                        -> LN2 -> MLP(gelu) -> +res
// B=4, L=4096, D=512, H=8, DH=64, MLP=2048, BS=128
// Strategy: TF32 mma.sync GEMMs (fp32 accum), fused epilogues, fp32 residuals.
// ---------------------------------------------------------------------------

#define NTOK 16384
#define D_   512
#define H_   8
#define DH_  64
#define MLPD 2048
#define BS_  128

// ---- scratch (device globals: allocation-free per harness rules) ----
__device__ float g_xin[NTOK * D_];
__device__ float g_q[NTOK * D_];
__device__ float g_k[NTOK * D_];
__device__ float g_v[NTOK * D_];
__device__ float g_ctx[NTOK * D_];
__device__ float g_x[NTOK * D_];
__device__ float g_y[NTOK * D_];
__device__ float g_h[NTOK * MLPD];
__device__ float g_wq[D_ * D_];
__device__ float g_wk[D_ * D_];
__device__ float g_wv[D_ * D_];
__device__ float g_wo[D_ * D_];
__device__ float g_w1[D_ * MLPD];
__device__ float g_w2[MLPD * D_];

// ---- helpers ----
__device__ __forceinline__ float rnd_tf32(float x) {
    unsigned u;
    asm("cvt.rna.tf32.f32 %0, %1;" : "=r"(u) : "f"(x));
    return __uint_as_float(u);
}

__device__ __forceinline__ float gelu_tanh(float x) {
    float x3 = x * x * x;
    float t = tanhf(0.7978845608028654f * (x + 0.044715f * x3));
    return 0.5f * x * (1.0f + t);
}

__device__ __forceinline__ void cp16(unsigned dst, const void* src) {
    asm volatile("cp.async.cg.shared.global [%0], [%1], 16;\n" :: "r"(dst), "l"(src));
}
#define CP_COMMIT asm volatile("cp.async.commit_group;\n")
#define CP_WAIT0  asm volatile("cp.async.wait_group 0;\n")

#define MMA8(c, a0, a1, a2, a3, b0, b1)                                        \
    asm volatile(                                                              \
        "mma.sync.aligned.m16n8k8.row.col.f32.tf32.tf32.f32 "                  \
        "{%0,%1,%2,%3},{%4,%5,%6,%7},{%8,%9},{%0,%1,%2,%3};"                   \
        : "+f"((c)[0]), "+f"((c)[1]), "+f"((c)[2]), "+f"((c)[3])               \
        : "r"(a0), "r"(a1), "r"(a2), "r"(a3), "r"(b0), "r"(b1))

// ---------------------------------------------------------------------------
// Weight pre-rounding: fp32 -> tf32-rounded fp32 (so GEMM inner loop is clean)
// ---------------------------------------------------------------------------
__global__ void round_tf32_kernel(const float* __restrict__ src,
                                  float* __restrict__ dst, int n) {
    for (int i = blockIdx.x * blockDim.x + threadIdx.x; i < n;
         i += gridDim.x * blockDim.x)
        dst[i] = rnd_tf32(src[i]);
}

// ---------------------------------------------------------------------------
// LayerNorm: one block per token row of 512, 128 threads, float4 I/O.
// ROUND: round output to tf32 (it feeds a GEMM A operand).
// ---------------------------------------------------------------------------
template <bool ROUND>
__global__ void __launch_bounds__(128)
ln_kernel(const float* __restrict__ in, const float* __restrict__ scale,
          const float* __restrict__ bias, float* __restrict__ out) {
    const int row = blockIdx.x;
    const int tid = threadIdx.x;
    float4 v = reinterpret_cast<const float4*>(in + (size_t)row * D_)[tid];
    float s  = v.x + v.y + v.z + v.w;
    float s2 = v.x * v.x + v.y * v.y + v.z * v.z + v.w * v.w;
#pragma unroll
    for (int o = 16; o > 0; o >>= 1) {
        s  += __shfl_xor_sync(0xffffffffu, s, o);
        s2 += __shfl_xor_sync(0xffffffffu, s2, o);
    }
    __shared__ float rs[4], rq[4];
    if ((tid & 31) == 0) { rs[tid >> 5] = s; rq[tid >> 5] = s2; }
    __syncthreads();
    s  = rs[0] + rs[1] + rs[2] + rs[3];
    s2 = rq[0] + rq[1] + rq[2] + rq[3];
    const float mu  = s * (1.0f / D_);
    const float var = s2 * (1.0f / D_) - mu * mu;
    const float inv = rsqrtf(var + 1e-6f);
    float4 sc = reinterpret_cast<const float4*>(scale)[tid];
    float4 bi = reinterpret_cast<const float4*>(bias)[tid];
    float4 r;
    r.x = (v.x - mu) * inv * sc.x + bi.x;
    r.y = (v.y - mu) * inv * sc.y + bi.y;
    r.z = (v.z - mu) * inv * sc.z + bi.z;
    r.w = (v.w - mu) * inv * sc.w + bi.w;
    if (ROUND) {
        r.x = rnd_tf32(r.x); r.y = rnd_tf32(r.y);
        r.z = rnd_tf32(r.z); r.w = rnd_tf32(r.w);
    }
    reinterpret_cast<float4*>(out + (size_t)row * D_)[tid] = r;
}

// ---------------------------------------------------------------------------
// TF32 GEMM: C[M,N] = A[M,K] * B[K,N], all row-major, fp32 accumulate.
// BM=128, BN=128, BK=32, 256 threads (8 warps: 2x4, warp tile 64x32).
// Double-buffered cp.async. Operands must already be tf32-rounded fp32.
// Epilogues:
//   0 EPI_ROUND   : C = tf32(acc)                       (qkv)
//   1 EPI_ADD     : C = acc + add[r,c]                  (o-proj + residual)
//   2 EPI_GELU    : C = tf32(gelu(acc + bias[c]))       (mlp1)
//   3 EPI_ADDBIAS : C = acc + bias[c] + add[r,c]        (mlp2 + residual)
// ---------------------------------------------------------------------------
constexpr int EPI_ROUND = 0, EPI_ADD = 1, EPI_GELU = 2, EPI_ADDBIAS = 3;
constexpr int GSA = 36;   // A smem stride (floats): 144B, 16B-aligned, conflict-free
constexpr int GSB = 136;  // B smem stride (floats): 544B, 16B-aligned, conflict-free
constexpr int GEMM_SMEM_BYTES = (2 * 128 * GSA + 2 * 32 * GSB) * 4;

template <int EPI>
__global__ void __launch_bounds__(256)
gemm_tf32(const float* __restrict__ A, const float* __restrict__ B,
          float* __restrict__ C, int M, int N, int K,
          const float* __restrict__ bias, const float* __restrict__ add) {
    extern __shared__ float sm[];
    float* Asb[2] = { sm, sm + 128 * GSA };
    float* Bsb[2] = { sm + 2 * 128 * GSA, sm + 2 * 128 * GSA + 32 * GSB };
    const unsigned base = (unsigned)__cvta_generic_to_shared(sm);
    const unsigned uA[2] = { base, base + 128 * GSA * 4 };
    const unsigned uB[2] = { base + 2 * 128 * GSA * 4,
                             base + (2 * 128 * GSA + 32 * GSB) * 4 };

    const int tid  = threadIdx.x;
    const int lane = tid & 31;
    const int w    = tid >> 5;
    const int wm   = (w >> 2) * 64;
    const int wn   = (w & 3) * 32;
    const int g    = lane >> 2, q = lane & 3;
    const int bm   = blockIdx.y * 128, bn = blockIdx.x * 128;

    const int ar = tid >> 3,  ac = (tid & 7) * 4;    // A tile: 128x32 fl, 4 f4/thr
    const int br = tid >> 5,  bc = (tid & 31) * 4;   // B tile: 32x128 fl, 4 f4/thr

    float acc[4][4][4];
#pragma unroll
    for (int i = 0; i < 4; i++)
#pragma unroll
        for (int j = 0; j < 4; j++)
#pragma unroll
            for (int l = 0; l < 4; l++) acc[i][j][l] = 0.0f;

    const int KT = K >> 5;

    {   // prologue: tile 0 -> buf 0
        const float* Ag = A + (size_t)bm * K;
        const float* Bg = B + bn;
#pragma unroll
        for (int t = 0; t < 4; t++)
            cp16(uA[0] + ((ar + t * 32) * GSA + ac) * 4,
                 Ag + (size_t)(ar + t * 32) * K + ac);
#pragma unroll
        for (int t = 0; t < 4; t++)
            cp16(uB[0] + ((br + t * 8) * GSB + bc) * 4,
                 Bg + (size_t)(br + t * 8) * N + bc);
        CP_COMMIT;
    }

    int buf = 0;
    for (int kt = 0; kt < KT; kt++) {
        CP_WAIT0;
        __syncthreads();
        if (kt + 1 < KT) {
            const int nb = buf ^ 1;
            const float* Ag = A + (size_t)bm * K + (kt + 1) * 32;
            const float* Bg = B + (size_t)(kt + 1) * 32 * N + bn;
#pragma unroll
            for (int t = 0; t < 4; t++)
                cp16(uA[nb] + ((ar + t * 32) * GSA + ac) * 4,
                     Ag + (size_t)(ar + t * 32) * K + ac);
#pragma unroll
            for (int t = 0; t < 4; t++)
                cp16(uB[nb] + ((br + t * 8) * GSB + bc) * 4,
                     Bg + (size_t)(br + t * 8) * N + bc);
            CP_COMMIT;
        }
        const float* as = Asb[buf];
        const float* bs = Bsb[buf];
#pragma unroll
        for (int ks = 0; ks < 4; ks++) {
            const int c = ks * 8 + q;
            unsigned af[4][4];
#pragma unroll
            for (int mt = 0; mt < 4; mt++) {
                const int r = wm + mt * 16 + g;
                af[mt][0] = __float_as_uint(as[r * GSA + c]);
                af[mt][1] = __float_as_uint(as[(r + 8) * GSA + c]);
                af[mt][2] = __float_as_uint(as[r * GSA + c + 4]);
                af[mt][3] = __float_as_uint(as[(r + 8) * GSA + c + 4]);
            }
            unsigned bf[4][2];
#pragma unroll
            for (int nt = 0; nt < 4; nt++) {
                const int cc = wn + nt * 8 + g;
                bf[nt][0] = __float_as_uint(bs[c * GSB + cc]);
                bf[nt][1] = __float_as_uint(bs[(c + 4) * GSB + cc]);
            }
#pragma unroll
            for (int mt = 0; mt < 4; mt++)
#pragma unroll
                for (int nt = 0; nt < 4; nt++)
                    MMA8(acc[mt][nt], af[mt][0], af[mt][1], af[mt][2], af[mt][3],
                         bf[nt][0], bf[nt][1]);
        }
        buf ^= 1;
    }

    // epilogue
#pragma unroll
    for (int mt = 0; mt < 4; mt++) {
#pragma unroll
        for (int nt = 0; nt < 4; nt++) {
            const int r0 = bm + wm + mt * 16 + g;
            const int c0 = bn + wn + nt * 8 + 2 * q;
#pragma unroll
            for (int half = 0; half < 2; half++) {
                const int r = r0 + half * 8;
                float v0 = acc[mt][nt][half * 2 + 0];
                float v1 = acc[mt][nt][half * 2 + 1];
                if (EPI == EPI_GELU || EPI == EPI_ADDBIAS) {
                    v0 += bias[c0]; v1 += bias[c0 + 1];
                }
                if (EPI == EPI_GELU) { v0 = gelu_tanh(v0); v1 = gelu_tanh(v1); }
                const size_t idx = (size_t)r * N + c0;
                if (EPI == EPI_ADD || EPI == EPI_ADDBIAS) {
                    v0 += add[idx]; v1 += add[idx + 1];
                }
                if (EPI == EPI_ROUND || EPI == EPI_GELU) {
                    v0 = rnd_tf32(v0); v1 = rnd_tf32(v1);
                }
                float2 o; o.x = v0; o.y = v1;
                *reinterpret_cast<float2*>(C + idx) = o;
            }
        }
    }
}

// ---------------------------------------------------------------------------
// Block-local attention: one CTA per (batch*block, head) = 1024 CTAs.
// S = (Q*DH^-0.5) K^T (tf32 mma) -> softmax (quad shuffles) -> P V (tf32 mma).
// 8 warps, each owns 16 query rows end-to-end (warp tile 16x128 / 16x64).
// P parked in smem aliased over Q/K (dead after S).
// ---------------------------------------------------------------------------
constexpr int ASQ = 68;   // Q/K smem stride
constexpr int ASV = 72;   // V smem stride
constexpr int ASP = 132;  // P smem stride
constexpr int ATT_SMEM_BYTES = (2 * 128 * ASQ + 128 * ASV) * 4;

__global__ void __launch_bounds__(256)
attn_kernel(const float* __restrict__ Q, const float* __restrict__ K,
            const float* __restrict__ V, float* __restrict__ CTX) {
    extern __shared__ float sm[];
    float* Qs = sm;
    float* Ks = sm + 128 * ASQ;
    float* Vs = sm + 2 * 128 * ASQ;
    float* Ps = sm;  // alias over Qs+Ks (128*132 = 16896 fl <= 17408 fl)

    const int tid = threadIdx.x, lane = tid & 31, w = tid >> 5;
    const int g = lane >> 2, q = lane & 3;
    const int blk = blockIdx.x >> 3;
    const int h   = blockIdx.x & 7;
    const int t0  = blk * BS_;
    const int fb  = h * DH_;

    // load Q (scaled by 1/8 = DH^-1/2, exact in tf32), K, V
#pragma unroll
    for (int t = 0; t < 8; t++) {
        const int idx = tid + t * 256;
        const int r = idx >> 4, c4 = (idx & 15) * 4;
        const size_t go = (size_t)(t0 + r) * D_ + fb + c4;
        float4 qv = *reinterpret_cast<const float4*>(Q + go);
        qv.x *= 0.125f; qv.y *= 0.125f; qv.z *= 0.125f; qv.w *= 0.125f;
        *reinterpret_cast<float4*>(Qs + r * ASQ + c4) = qv;
        *reinterpret_cast<float4*>(Ks + r * ASQ + c4) =
            *reinterpret_cast<const float4*>(K + go);
        *reinterpret_cast<float4*>(Vs + r * ASV + c4) =
            *reinterpret_cast<const float4*>(V + go);
    }
    __syncthreads();

    const int mrow = w * 16;
    float sacc[16][4];
#pragma unroll
    for (int nt = 0; nt < 16; nt++)
#pragma unroll
        for (int l = 0; l < 4; l++) sacc[nt][l] = 0.0f;

    // S = Q K^T   (K=64 -> 8 ksteps)
#pragma unroll
    for (int kt = 0; kt < 8; kt++) {
        const int c = kt * 8 + q;
        const unsigned a0 = __float_as_uint(Qs[(mrow + g) * ASQ + c]);
        const unsigned a1 = __float_as_uint(Qs[(mrow + g + 8) * ASQ + c]);
        const unsigned a2 = __float_as_uint(Qs[(mrow + g) * ASQ + c + 4]);
        const unsigned a3 = __float_as_uint(Qs[(mrow + g + 8) * ASQ + c + 4]);
#pragma unroll
        for (int nt = 0; nt < 16; nt++) {
            const unsigned b0 = __float_as_uint(Ks[(nt * 8 + g) * ASQ + c]);
            const unsigned b1 = __float_as_uint(Ks[(nt * 8 + g) * ASQ + c + 4]);
            MMA8(sacc[nt], a0, a1, a2, a3, b0, b1);
        }
    }
    __syncthreads();  // all warps done reading Qs/Ks before Ps overwrites them

    // softmax over 128 cols; each row lives in one quad of lanes
    float m0 = -1e30f, m1 = -1e30f;
#pragma unroll
    for (int nt = 0; nt < 16; nt++) {
        m0 = fmaxf(m0, fmaxf(sacc[nt][0], sacc[nt][1]));
        m1 = fmaxf(m1, fmaxf(sacc[nt][2], sacc[nt][3]));
    }
    m0 = fmaxf(m0, __shfl_xor_sync(0xffffffffu, m0, 1));
    m0 = fmaxf(m0, __shfl_xor_sync(0xffffffffu, m0, 2));
    m1 = fmaxf(m1, __shfl_xor_sync(0xffffffffu, m1, 1));
    m1 = fmaxf(m1, __shfl_xor_sync(0xffffffffu, m1, 2));
    float s0 = 0.0f, s1 = 0.0f;
#pragma unroll
    for (int nt = 0; nt < 16; nt++) {
        sacc[nt][0] = expf(sacc[nt][0] - m0); s0 += sacc[nt][0];
        sacc[nt][1] = expf(sacc[nt][1] - m0); s0 += sacc[nt][1];
        sacc[nt][2] = expf(sacc[nt][2] - m1); s1 += sacc[nt][2];
        sacc[nt][3] = expf(sacc[nt][3] - m1); s1 += sacc[nt][3];
    }
    s0 += __shfl_xor_sync(0xffffffffu, s0, 1);
    s0 += __shfl_xor_sync(0xffffffffu, s0, 2);
    s1 += __shfl_xor_sync(0xffffffffu, s1, 1);
    s1 += __shfl_xor_sync(0xffffffffu, s1, 2);
    const float i0 = 1.0f / s0, i1 = 1.0f / s1;

#pragma unroll
    for (int nt = 0; nt < 16; nt++) {
        const int cc = nt * 8 + 2 * q;
        float2 p0; p0.x = rnd_tf32(sacc[nt][0] * i0);
        p0.y = rnd_tf32(sacc[nt][1] * i0);
        *reinterpret_cast<float2*>(Ps + (mrow + g) * ASP + cc) = p0;
        float2 p1; p1.x = rnd_tf32(sacc[nt][2] * i1);
        p1.y = rnd_tf32(sacc[nt][3] * i1);
        *reinterpret_cast<float2*>(Ps + (mrow + g + 8) * ASP + cc) = p1;
    }
    __syncwarp();  // same-warp produce->consume of this warp's Ps rows

    // ctx = P V   (K=128 -> 16 ksteps, N=64 -> 8 ntiles)
    float o[8][4];
#pragma unroll
    for (int nt = 0; nt < 8; nt++)
#pragma unroll
        for (int l = 0; l < 4; l++) o[nt][l] = 0.0f;
#pragma unroll
    for (int kt = 0; kt < 16; kt++) {
        const int c = kt * 8 + q;
        const unsigned a0 = __float_as_uint(Ps[(mrow + g) * ASP + c]);
        const unsigned a1 = __float_as_uint(Ps[(mrow + g + 8) * ASP + c]);
        const unsigned a2 = __float_as_uint(Ps[(mrow + g) * ASP + c + 4]);
        const unsigned a3 = __float_as_uint(Ps[(mrow + g + 8) * ASP + c + 4]);
#pragma unroll
        for (int nt = 0; nt < 8; nt++) {
            const unsigned b0 = __float_as_uint(Vs[c * ASV + nt * 8 + g]);
            const unsigned b1 = __float_as_uint(Vs[(c + 4) * ASV + nt * 8 + g]);
            MMA8(o[nt], a0, a1, a2, a3, b0, b1);
        }
    }

    // write ctx, tf32-rounded (feeds O-proj GEMM)
#pragma unroll
    for (int nt = 0; nt < 8; nt++) {
        const int d0 = nt * 8 + 2 * q;
        const int r = t0 + mrow + g;
        float2 v0; v0.x = rnd_tf32(o[nt][0]); v0.y = rnd_tf32(o[nt][1]);
        *reinterpret_cast<float2*>(CTX + (size_t)r * D_ + fb + d0) = v0;
        float2 v1; v1.x = rnd_tf32(o[nt][2]); v1.y = rnd_tf32(o[nt][3]);
        *reinterpret_cast<float2*>(CTX + (size_t)(r + 8) * D_ + fb + d0) = v1;
    }
}

// ---------------------------------------------------------------------------
// launch
// ---------------------------------------------------------------------------
extern "C" void kernel_launch(void* const* d_in, const int* in_sizes, int n_in,
                              void* d_out, int out_size) {
    const float* inputs = (const float*)d_in[0];
    const float* ln1s   = (const float*)d_in[1];
    const float* ln1b   = (const float*)d_in[2];
    const float* wq     = (const float*)d_in[3];
    const float* wk     = (const float*)d_in[4];
    const float* wv     = (const float*)d_in[5];
    const float* wo     = (const float*)d_in[6];
    const float* ln2s   = (const float*)d_in[7];
    const float* ln2b   = (const float*)d_in[8];
    const float* w1     = (const float*)d_in[9];
    const float* b1     = (const float*)d_in[10];
    const float* w2     = (const float*)d_in[11];
    const float* b2     = (const float*)d_in[12];
    float* out = (float*)d_out;

    void *p_xin, *p_q, *p_k, *p_v, *p_ctx, *p_x, *p_y, *p_h;
    void *p_wq, *p_wk, *p_wv, *p_wo, *p_w1, *p_w2;
    cudaGetSymbolAddress(&p_xin, g_xin);
    cudaGetSymbolAddress(&p_q, g_q);
    cudaGetSymbolAddress(&p_k, g_k);
    cudaGetSymbolAddress(&p_v, g_v);
    cudaGetSymbolAddress(&p_ctx, g_ctx);
    cudaGetSymbolAddress(&p_x, g_x);
    cudaGetSymbolAddress(&p_y, g_y);
    cudaGetSymbolAddress(&p_h, g_h);
    cudaGetSymbolAddress(&p_wq, g_wq);
    cudaGetSymbolAddress(&p_wk, g_wk);
    cudaGetSymbolAddress(&p_wv, g_wv);
    cudaGetSymbolAddress(&p_wo, g_wo);
    cudaGetSymbolAddress(&p_w1, g_w1);
    cudaGetSymbolAddress(&p_w2, g_w2);

    cudaFuncSetAttribute(gemm_tf32<EPI_ROUND>,
        cudaFuncAttributeMaxDynamicSharedMemorySize, GEMM_SMEM_BYTES);
    cudaFuncSetAttribute(gemm_tf32<EPI_ADD>,
        cudaFuncAttributeMaxDynamicSharedMemorySize, GEMM_SMEM_BYTES);
    cudaFuncSetAttribute(gemm_tf32<EPI_GELU>,
        cudaFuncAttributeMaxDynamicSharedMemorySize, GEMM_SMEM_BYTES);
    cudaFuncSetAttribute(gemm_tf32<EPI_ADDBIAS>,
        cudaFuncAttributeMaxDynamicSharedMemorySize, GEMM_SMEM_BYTES);
    cudaFuncSetAttribute(attn_kernel,
        cudaFuncAttributeMaxDynamicSharedMemorySize, ATT_SMEM_BYTES);

    // 1) pre-round weights to tf32
    round_tf32_kernel<<<256, 256>>>(wq, (float*)p_wq, D_ * D_);
    round_tf32_kernel<<<256, 256>>>(wk, (float*)p_wk, D_ * D_);
    round_tf32_kernel<<<256, 256>>>(wv, (float*)p_wv, D_ * D_);
    round_tf32_kernel<<<256, 256>>>(wo, (float*)p_wo, D_ * D_);
    round_tf32_kernel<<<512, 256>>>(w1, (float*)p_w1, D_ * MLPD);
    round_tf32_kernel<<<512, 256>>>(w2, (float*)p_w2, MLPD * D_);

    // 2) LN1 (tf32-rounded output)
    ln_kernel<true><<<NTOK, 128>>>(inputs, ln1s, ln1b, (float*)p_xin);

    // 3) QKV projections
    dim3 g512(4, 128), g2048(16, 128);
    gemm_tf32<EPI_ROUND><<<g512, 256, GEMM_SMEM_BYTES>>>(
        (float*)p_xin, (float*)p_wq, (float*)p_q, NTOK, D_, D_, nullptr, nullptr);
    gemm_tf32<EPI_ROUND><<<g512, 256, GEMM_SMEM_BYTES>>>(
        (float*)p_xin, (float*)p_wk, (float*)p_k, NTOK, D_, D_, nullptr, nullptr);
    gemm_tf32<EPI_ROUND><<<g512, 256, GEMM_SMEM_BYTES>>>(
        (float*)p_xin, (float*)p_wv, (float*)p_v, NTOK, D_, D_, nullptr, nullptr);

    // 4) block-local attention
    attn_kernel<<<1024, 256, ATT_SMEM_BYTES>>>(
        (float*)p_q, (float*)p_k, (float*)p_v, (float*)p_ctx);

    // 5) O projection + residual -> x
    gemm_tf32<EPI_ADD><<<g512, 256, GEMM_SMEM_BYTES>>>(
        (float*)p_ctx, (float*)p_wo, (float*)p_x, NTOK, D_, D_, nullptr, inputs);

    // 6) LN2 (tf32-rounded)
    ln_kernel<true><<<NTOK, 128>>>((float*)p_x, ln2s, ln2b, (float*)p_y);

    // 7) MLP1: gelu(y W1 + b1) -> h (tf32-rounded)
    gemm_tf32<EPI_GELU><<<g2048, 256, GEMM_SMEM_BYTES>>>(
        (float*)p_y, (float*)p_w1, (float*)p_h, NTOK, MLPD, D_, b1, nullptr);

    // 8) MLP2: h W2 + b2 + x -> out
    gemm_tf32<EPI_ADDBIAS><<<g512, 256, GEMM_SMEM_BYTES>>>(
        (float*)p_h, (float*)p_w2, out, NTOK, D_, MLPD, b2, (float*)p_x);
}

// round 5
// speedup vs baseline: 2.1526x; 2.1526x over previous
#include <cuda_runtime.h>
#include <cuda_fp16.h>

// ---------------------------------------------------------------------------
// LocalTransformerBlock, fp16 mma.sync (m16n8k16, fp32 accum) GEMMs.
// compute_100 target: no tcgen05 available (ptxas rejects it) — legacy mma path.
// B=4, L=4096, D=512, H=8, DH=64, MLP=2048, BS=128
// ---------------------------------------------------------------------------

#define NTOK 16384
#define D_   512
#define DH_  64
#define QKVN 1536
#define MLPD 2048
#define BS_  128

// ---- device scratch ----
__device__ __half g_xin[NTOK * D_];
__device__ __half g_qkv[NTOK * QKVN];
__device__ __half g_ctx[NTOK * D_];
__device__ float  g_x[NTOK * D_];
__device__ __half g_y[NTOK * D_];
__device__ __half g_h[NTOK * MLPD];
__device__ __half g_wqkv[QKVN * D_];   // [N][K] transposed
__device__ __half g_wot[D_ * D_];
__device__ __half g_w1t[MLPD * D_];
__device__ __half g_w2t[D_ * MLPD];

// ---- helpers ----
__device__ __forceinline__ float rnd_tf32(float x) {
    unsigned u;
    asm("cvt.rna.tf32.f32 %0, %1;" : "=r"(u) : "f"(x));
    return __uint_as_float(u);
}
__device__ __forceinline__ float gelu_tanh(float x) {
    float a = 0.7978845608028654f * (x + 0.044715f * x * x * x);
    float t;
    asm("tanh.approx.f32 %0, %1;" : "=f"(t) : "f"(a));
    return 0.5f * x * (1.0f + t);
}
__device__ __forceinline__ void cp16(unsigned dst, const void* src) {
    asm volatile("cp.async.cg.shared.global [%0], [%1], 16;\n" :: "r"(dst), "l"(src));
}
#define CP_COMMIT asm volatile("cp.async.commit_group;\n")
#define CP_WAIT0  asm volatile("cp.async.wait_group 0;\n")

// fp16 mma m16n8k16, fp32 accum
#define MMA16(c, a0, a1, a2, a3, b0, b1)                                       \
    asm volatile(                                                              \
        "mma.sync.aligned.m16n8k16.row.col.f32.f16.f16.f32 "                   \
        "{%0,%1,%2,%3},{%4,%5,%6,%7},{%8,%9},{%0,%1,%2,%3};"                   \
        : "+f"((c)[0]), "+f"((c)[1]), "+f"((c)[2]), "+f"((c)[3])               \
        : "r"(a0), "r"(a1), "r"(a2), "r"(a3), "r"(b0), "r"(b1))

// tf32 mma m16n8k8 (attention)
#define MMA8(c, a0, a1, a2, a3, b0, b1)                                        \
    asm volatile(                                                              \
        "mma.sync.aligned.m16n8k8.row.col.f32.tf32.tf32.f32 "                  \
        "{%0,%1,%2,%3},{%4,%5,%6,%7},{%8,%9},{%0,%1,%2,%3};"                   \
        : "+f"((c)[0]), "+f"((c)[1]), "+f"((c)[2]), "+f"((c)[3])               \
        : "r"(a0), "r"(a1), "r"(a2), "r"(a3), "r"(b0), "r"(b1))

// ---------------------------------------------------------------------------
// Weight prep: transpose + fp16 convert.  dst[n*R + k] = h(src[k*C + n])
// ---------------------------------------------------------------------------
__global__ void __launch_bounds__(256)
transpose_h(const float* __restrict__ src, __half* __restrict__ dst,
            int R, int C) {
    __shared__ float t[32][33];
    const int n0 = blockIdx.x * 32, k0 = blockIdx.y * 32;
    const int x = threadIdx.x, y = threadIdx.y;
#pragma unroll
    for (int i = 0; i < 32; i += 8)
        t[y + i][x] = src[(size_t)(k0 + y + i) * C + n0 + x];
    __syncthreads();
#pragma unroll
    for (int i = 0; i < 32; i += 8)
        dst[(size_t)(n0 + y + i) * R + k0 + x] = __float2half_rn(t[x][y + i]);
}

__global__ void __launch_bounds__(256)
prep_qkv(const float* __restrict__ wq, const float* __restrict__ wk,
         const float* __restrict__ wv, __half* __restrict__ dst) {
    const float* src = blockIdx.z == 0 ? wq : (blockIdx.z == 1 ? wk : wv);
    __half* d = dst + (size_t)blockIdx.z * D_ * D_;
    __shared__ float t[32][33];
    const int n0 = blockIdx.x * 32, k0 = blockIdx.y * 32;
    const int x = threadIdx.x, y = threadIdx.y;
#pragma unroll
    for (int i = 0; i < 32; i += 8)
        t[y + i][x] = src[(size_t)(k0 + y + i) * D_ + n0 + x];
    __syncthreads();
#pragma unroll
    for (int i = 0; i < 32; i += 8)
        d[(size_t)(n0 + y + i) * D_ + k0 + x] = __float2half_rn(t[x][y + i]);
}

// ---------------------------------------------------------------------------
// LayerNorm: fp32 in -> fp16 out. One block per token row, 128 threads.
// ---------------------------------------------------------------------------
__global__ void __launch_bounds__(128)
ln_kernel(const float* __restrict__ in, const float* __restrict__ scale,
          const float* __restrict__ bias, __half* __restrict__ out) {
    const int row = blockIdx.x;
    const int tid = threadIdx.x;
    float4 v = reinterpret_cast<const float4*>(in + (size_t)row * D_)[tid];
    float s  = v.x + v.y + v.z + v.w;
    float s2 = v.x * v.x + v.y * v.y + v.z * v.z + v.w * v.w;
#pragma unroll
    for (int o = 16; o > 0; o >>= 1) {
        s  += __shfl_xor_sync(0xffffffffu, s, o);
        s2 += __shfl_xor_sync(0xffffffffu, s2, o);
    }
    __shared__ float rs[4], rq[4];
    if ((tid & 31) == 0) { rs[tid >> 5] = s; rq[tid >> 5] = s2; }
    __syncthreads();
    s  = rs[0] + rs[1] + rs[2] + rs[3];
    s2 = rq[0] + rq[1] + rq[2] + rq[3];
    const float mu  = s * (1.0f / D_);
    const float var = s2 * (1.0f / D_) - mu * mu;
    const float inv = rsqrtf(var + 1e-6f);
    float4 sc = reinterpret_cast<const float4*>(scale)[tid];
    float4 bi = reinterpret_cast<const float4*>(bias)[tid];
    __half2 h0 = __floats2half2_rn((v.x - mu) * inv * sc.x + bi.x,
                                   (v.y - mu) * inv * sc.y + bi.y);
    __half2 h1 = __floats2half2_rn((v.z - mu) * inv * sc.z + bi.z,
                                   (v.w - mu) * inv * sc.w + bi.w);
    __half2* op = reinterpret_cast<__half2*>(out + (size_t)row * D_) + tid * 2;
    op[0] = h0; op[1] = h1;
}

// ---------------------------------------------------------------------------
// fp16 GEMM: C[M,N] = A[M,K] (row-major fp16) * Bt[N,K] (K-major fp16),
// fp32 accumulate. BM=128, BN=128, BK=64, 128 threads (4 warps, 2x2,
// warp tile 64x64). Double-buffered cp.async, XOR-swizzled smem.
// ---------------------------------------------------------------------------
constexpr int EPI_H = 0;        // C fp16 = acc                    (qkv)
constexpr int EPI_ADD_F = 1;    // C fp32 = acc + add              (o-proj)
constexpr int EPI_GELU_H = 2;   // C fp16 = gelu(acc + bias)       (mlp1)
constexpr int EPI_ADDBIAS_F = 3;// C fp32 = acc + bias + add       (mlp2)

constexpr int STAGE = 32768;                 // 16KB A + 16KB B
constexpr int GM_DSMEM = 2 * STAGE + 1024;

template <int EPI>
__global__ void __launch_bounds__(128)
gemm_h(const __half* __restrict__ A, const __half* __restrict__ Bt,
       void* __restrict__ Cv, int M, int N, int K,
       const float* __restrict__ bias, const float* __restrict__ add) {
    extern __shared__ float dyn[];
    char* smf = (char*)(((size_t)(char*)dyn + 1023) & ~(size_t)1023);
    const unsigned sbase = (unsigned)__cvta_generic_to_shared(smf);

    const int tid = threadIdx.x, lane = tid & 31, w = tid >> 5;
    const int g = lane >> 2, q = lane & 3;
    const int wm = (w >> 1) * 64, wn = (w & 1) * 64;
    const int bm = blockIdx.y * 128, bn = blockIdx.x * 128;
    const int KT = K >> 6;

    float acc[4][8][4];
#pragma unroll
    for (int mt = 0; mt < 4; mt++)
#pragma unroll
        for (int nt = 0; nt < 8; nt++)
#pragma unroll
            for (int l = 0; l < 4; l++) acc[mt][nt][l] = 0.0f;

    auto load_stage = [&](int s, int kt) {
        const unsigned ua = sbase + s * STAGE;
        const unsigned ub = ua + 16384;
        const __half* Ag = A + (size_t)bm * K + kt * 64;
        const __half* Bg = Bt + (size_t)bn * K + kt * 64;
#pragma unroll
        for (int t = 0; t < 8; t++) {
            const int idx = tid + t * 128;
            const int r = idx >> 3, c = idx & 7;
            cp16(ua + r * 128 + ((c ^ (r & 7)) << 4), Ag + (size_t)r * K + c * 8);
        }
#pragma unroll
        for (int t = 0; t < 8; t++) {
            const int idx = tid + t * 128;
            const int r = idx >> 3, c = idx & 7;
            cp16(ub + r * 128 + ((c ^ (r & 7)) << 4), Bg + (size_t)r * K + c * 8);
        }
        CP_COMMIT;
    };

    load_stage(0, 0);

    for (int kt = 0; kt < KT; kt++) {
        CP_WAIT0;
        __syncthreads();
        if (kt + 1 < KT) load_stage((kt + 1) & 1, kt + 1);

        const char* smA = smf + (kt & 1) * STAGE;
        const char* smB = smA + 16384;
#pragma unroll
        for (int ks = 0; ks < 4; ks++) {
            const int ch0 = 2 * ks, ch1 = 2 * ks + 1;
            unsigned af[4][4];
#pragma unroll
            for (int mt = 0; mt < 4; mt++) {
                const int r0 = wm + mt * 16 + g;
                const int s7 = r0 & 7;
                af[mt][0] = *(const unsigned*)(smA + r0 * 128 + ((ch0 ^ s7) << 4) + 4 * q);
                af[mt][1] = *(const unsigned*)(smA + (r0 + 8) * 128 + ((ch0 ^ ((r0 + 8) & 7)) << 4) + 4 * q);
                af[mt][2] = *(const unsigned*)(smA + r0 * 128 + ((ch1 ^ s7) << 4) + 4 * q);
                af[mt][3] = *(const unsigned*)(smA + (r0 + 8) * 128 + ((ch1 ^ ((r0 + 8) & 7)) << 4) + 4 * q);
            }
#pragma unroll
            for (int nt = 0; nt < 8; nt++) {
                const int cr = wn + nt * 8 + g;
                const int s7 = cr & 7;
                const unsigned b0 = *(const unsigned*)(smB + cr * 128 + ((ch0 ^ s7) << 4) + 4 * q);
                const unsigned b1 = *(const unsigned*)(smB + cr * 128 + ((ch1 ^ s7) << 4) + 4 * q);
#pragma unroll
                for (int mt = 0; mt < 4; mt++)
                    MMA16(acc[mt][nt], af[mt][0], af[mt][1], af[mt][2], af[mt][3],
                          b0, b1);
            }
        }
    }

    // ---- epilogue ----
#pragma unroll
    for (int mt = 0; mt < 4; mt++) {
#pragma unroll
        for (int nt = 0; nt < 8; nt++) {
            const int r0 = bm + wm + mt * 16 + g;
            const int c0 = bn + wn + nt * 8 + 2 * q;
            float bx = 0.0f, by = 0.0f;
            if (EPI == EPI_GELU_H || EPI == EPI_ADDBIAS_F) {
                float2 bv = *reinterpret_cast<const float2*>(bias + c0);
                bx = bv.x; by = bv.y;
            }
#pragma unroll
            for (int half = 0; half < 2; half++) {
                const int r = r0 + half * 8;
                float v0 = acc[mt][nt][half * 2 + 0] + bx;
                float v1 = acc[mt][nt][half * 2 + 1] + by;
                const size_t idx = (size_t)r * N + c0;
                if (EPI == EPI_GELU_H) { v0 = gelu_tanh(v0); v1 = gelu_tanh(v1); }
                if (EPI == EPI_ADD_F || EPI == EPI_ADDBIAS_F) {
                    float2 av = *reinterpret_cast<const float2*>(add + idx);
                    v0 += av.x; v1 += av.y;
                    float2 o; o.x = v0; o.y = v1;
                    *reinterpret_cast<float2*>((float*)Cv + idx) = o;
                } else {
                    *reinterpret_cast<__half2*>((__half*)Cv + idx) =
                        __floats2half2_rn(v0, v1);
                }
            }
        }
    }
}

// ---------------------------------------------------------------------------
// Block-local attention (tf32 mma path, proven in R1). fp16 in/out.
// CTA per (block, head); QKV fused input stride 1536.
// ---------------------------------------------------------------------------
constexpr int ASQ = 68, ASV = 72, ASP = 132;
constexpr int ATT_SMEM_BYTES = (2 * 128 * ASQ + 128 * ASV) * 4;

__global__ void __launch_bounds__(256)
attn_kernel(const __half* __restrict__ QKV, __half* __restrict__ CTX) {
    extern __shared__ float sm[];
    float* Qs = sm;
    float* Ks = sm + 128 * ASQ;
    float* Vs = sm + 2 * 128 * ASQ;
    float* Ps = sm;  // alias over Qs+Ks

    const int tid = threadIdx.x, lane = tid & 31, w = tid >> 5;
    const int g = lane >> 2, q = lane & 3;
    const int blk = blockIdx.x >> 3;
    const int h   = blockIdx.x & 7;
    const int t0  = blk * BS_;
    const int fb  = h * DH_;

#pragma unroll
    for (int t = 0; t < 8; t++) {
        const int idx = tid + t * 256;
        const int r = idx >> 4, c4 = (idx & 15) * 4;
        const size_t rowb = (size_t)(t0 + r) * QKVN;
        const __half2* qp = reinterpret_cast<const __half2*>(QKV + rowb + fb + c4);
        const __half2* kp = reinterpret_cast<const __half2*>(QKV + rowb + 512 + fb + c4);
        const __half2* vp = reinterpret_cast<const __half2*>(QKV + rowb + 1024 + fb + c4);
        float2 q0 = __half22float2(qp[0]), q1 = __half22float2(qp[1]);
        float2 k0 = __half22float2(kp[0]), k1 = __half22float2(kp[1]);
        float2 v0 = __half22float2(vp[0]), v1 = __half22float2(vp[1]);
        float4 qv; qv.x = q0.x * 0.125f; qv.y = q0.y * 0.125f;
        qv.z = q1.x * 0.125f; qv.w = q1.y * 0.125f;
        float4 kv; kv.x = k0.x; kv.y = k0.y; kv.z = k1.x; kv.w = k1.y;
        float4 vv; vv.x = v0.x; vv.y = v0.y; vv.z = v1.x; vv.w = v1.y;
        *reinterpret_cast<float4*>(Qs + r * ASQ + c4) = qv;
        *reinterpret_cast<float4*>(Ks + r * ASQ + c4) = kv;
        *reinterpret_cast<float4*>(Vs + r * ASV + c4) = vv;
    }
    __syncthreads();

    const int mrow = w * 16;
    float sacc[16][4];
#pragma unroll
    for (int nt = 0; nt < 16; nt++)
#pragma unroll
        for (int l = 0; l < 4; l++) sacc[nt][l] = 0.0f;

#pragma unroll
    for (int kt = 0; kt < 8; kt++) {
        const int c = kt * 8 + q;
        const unsigned a0 = __float_as_uint(Qs[(mrow + g) * ASQ + c]);
        const unsigned a1 = __float_as_uint(Qs[(mrow + g + 8) * ASQ + c]);
        const unsigned a2 = __float_as_uint(Qs[(mrow + g) * ASQ + c + 4]);
        const unsigned a3 = __float_as_uint(Qs[(mrow + g + 8) * ASQ + c + 4]);
#pragma unroll
        for (int nt = 0; nt < 16; nt++) {
            const unsigned b0 = __float_as_uint(Ks[(nt * 8 + g) * ASQ + c]);
            const unsigned b1 = __float_as_uint(Ks[(nt * 8 + g) * ASQ + c + 4]);
            MMA8(sacc[nt], a0, a1, a2, a3, b0, b1);
        }
    }
    __syncthreads();

    float m0 = -1e30f, m1 = -1e30f;
#pragma unroll
    for (int nt = 0; nt < 16; nt++) {
        m0 = fmaxf(m0, fmaxf(sacc[nt][0], sacc[nt][1]));
        m1 = fmaxf(m1, fmaxf(sacc[nt][2], sacc[nt][3]));
    }
    m0 = fmaxf(m0, __shfl_xor_sync(0xffffffffu, m0, 1));
    m0 = fmaxf(m0, __shfl_xor_sync(0xffffffffu, m0, 2));
    m1 = fmaxf(m1, __shfl_xor_sync(0xffffffffu, m1, 1));
    m1 = fmaxf(m1, __shfl_xor_sync(0xffffffffu, m1, 2));
    float s0 = 0.0f, s1 = 0.0f;
#pragma unroll
    for (int nt = 0; nt < 16; nt++) {
        sacc[nt][0] = expf(sacc[nt][0] - m0); s0 += sacc[nt][0];
        sacc[nt][1] = expf(sacc[nt][1] - m0); s0 += sacc[nt][1];
        sacc[nt][2] = expf(sacc[nt][2] - m1); s1 += sacc[nt][2];
        sacc[nt][3] = expf(sacc[nt][3] - m1); s1 += sacc[nt][3];
    }
    s0 += __shfl_xor_sync(0xffffffffu, s0, 1);
    s0 += __shfl_xor_sync(0xffffffffu, s0, 2);
    s1 += __shfl_xor_sync(0xffffffffu, s1, 1);
    s1 += __shfl_xor_sync(0xffffffffu, s1, 2);
    const float i0 = 1.0f / s0, i1 = 1.0f / s1;

#pragma unroll
    for (int nt = 0; nt < 16; nt++) {
        const int cc = nt * 8 + 2 * q;
        float2 p0; p0.x = rnd_tf32(sacc[nt][0] * i0);
        p0.y = rnd_tf32(sacc[nt][1] * i0);
        *reinterpret_cast<float2*>(Ps + (mrow + g) * ASP + cc) = p0;
        float2 p1; p1.x = rnd_tf32(sacc[nt][2] * i1);
        p1.y = rnd_tf32(sacc[nt][3] * i1);
        *reinterpret_cast<float2*>(Ps + (mrow + g + 8) * ASP + cc) = p1;
    }
    __syncwarp();

    float o[8][4];
#pragma unroll
    for (int nt = 0; nt < 8; nt++)
#pragma unroll
        for (int l = 0; l < 4; l++) o[nt][l] = 0.0f;
#pragma unroll
    for (int kt = 0; kt < 16; kt++) {
        const int c = kt * 8 + q;
        const unsigned a0 = __float_as_uint(Ps[(mrow + g) * ASP + c]);
        const unsigned a1 = __float_as_uint(Ps[(mrow + g + 8) * ASP + c]);
        const unsigned a2 = __float_as_uint(Ps[(mrow + g) * ASP + c + 4]);
        const unsigned a3 = __float_as_uint(Ps[(mrow + g + 8) * ASP + c + 4]);
#pragma unroll
        for (int nt = 0; nt < 8; nt++) {
            const unsigned b0 = __float_as_uint(Vs[c * ASV + nt * 8 + g]);
            const unsigned b1 = __float_as_uint(Vs[(c + 4) * ASV + nt * 8 + g]);
            MMA8(o[nt], a0, a1, a2, a3, b0, b1);
        }
    }

#pragma unroll
    for (int nt = 0; nt < 8; nt++) {
        const int d0 = nt * 8 + 2 * q;
        const int r = t0 + mrow + g;
        *reinterpret_cast<__half2*>(CTX + (size_t)r * D_ + fb + d0) =
            __floats2half2_rn(o[nt][0], o[nt][1]);
        *reinterpret_cast<__half2*>(CTX + (size_t)(r + 8) * D_ + fb + d0) =
            __floats2half2_rn(o[nt][2], o[nt][3]);
    }
}

// ---------------------------------------------------------------------------
// launch
// ---------------------------------------------------------------------------
extern "C" void kernel_launch(void* const* d_in, const int* in_sizes, int n_in,
                              void* d_out, int out_size) {
    const float* inputs = (const float*)d_in[0];
    const float* ln1s   = (const float*)d_in[1];
    const float* ln1b   = (const float*)d_in[2];
    const float* wq     = (const float*)d_in[3];
    const float* wk     = (const float*)d_in[4];
    const float* wv     = (const float*)d_in[5];
    const float* wo     = (const float*)d_in[6];
    const float* ln2s   = (const float*)d_in[7];
    const float* ln2b   = (const float*)d_in[8];
    const float* w1     = (const float*)d_in[9];
    const float* b1     = (const float*)d_in[10];
    const float* w2     = (const float*)d_in[11];
    const float* b2     = (const float*)d_in[12];
    float* out = (float*)d_out;

    void *p_xin, *p_qkv, *p_ctx, *p_x, *p_y, *p_h;
    void *p_wqkv, *p_wot, *p_w1t, *p_w2t;
    cudaGetSymbolAddress(&p_xin, g_xin);
    cudaGetSymbolAddress(&p_qkv, g_qkv);
    cudaGetSymbolAddress(&p_ctx, g_ctx);
    cudaGetSymbolAddress(&p_x, g_x);
    cudaGetSymbolAddress(&p_y, g_y);
    cudaGetSymbolAddress(&p_h, g_h);
    cudaGetSymbolAddress(&p_wqkv, g_wqkv);
    cudaGetSymbolAddress(&p_wot, g_wot);
    cudaGetSymbolAddress(&p_w1t, g_w1t);
    cudaGetSymbolAddress(&p_w2t, g_w2t);

    cudaFuncSetAttribute(gemm_h<EPI_H>,
        cudaFuncAttributeMaxDynamicSharedMemorySize, GM_DSMEM);
    cudaFuncSetAttribute(gemm_h<EPI_ADD_F>,
        cudaFuncAttributeMaxDynamicSharedMemorySize, GM_DSMEM);
    cudaFuncSetAttribute(gemm_h<EPI_GELU_H>,
        cudaFuncAttributeMaxDynamicSharedMemorySize, GM_DSMEM);
    cudaFuncSetAttribute(gemm_h<EPI_ADDBIAS_F>,
        cudaFuncAttributeMaxDynamicSharedMemorySize, GM_DSMEM);
    cudaFuncSetAttribute(attn_kernel,
        cudaFuncAttributeMaxDynamicSharedMemorySize, ATT_SMEM_BYTES);

    dim3 tb(32, 8);

    // launches 0-3: weight prep (transpose + fp16)
    prep_qkv<<<dim3(16, 16, 3), tb>>>(wq, wk, wv, (__half*)p_wqkv);
    transpose_h<<<dim3(16, 16), tb>>>(wo, (__half*)p_wot, D_, D_);
    transpose_h<<<dim3(64, 16), tb>>>(w1, (__half*)p_w1t, D_, MLPD);
    transpose_h<<<dim3(16, 64), tb>>>(w2, (__half*)p_w2t, MLPD, D_);

    // launch 4: LN1
    ln_kernel<<<NTOK, 128>>>(inputs, ln1s, ln1b, (__half*)p_xin);

    // launch 5: fused QKV GEMM [16384,512] x [1536,512]^T  (ncu -s 5 target)
    gemm_h<EPI_H><<<dim3(12, 128), 128, GM_DSMEM>>>(
        (__half*)p_xin, (__half*)p_wqkv, p_qkv,
        NTOK, QKVN, D_, nullptr, nullptr);

    // launch 6: attention
    attn_kernel<<<1024, 256, ATT_SMEM_BYTES>>>((__half*)p_qkv, (__half*)p_ctx);

    // launch 7: O projection + residual -> x (fp32)
    gemm_h<EPI_ADD_F><<<dim3(4, 128), 128, GM_DSMEM>>>(
        (__half*)p_ctx, (__half*)p_wot, p_x,
        NTOK, D_, D_, nullptr, inputs);

    // launch 8: LN2
    ln_kernel<<<NTOK, 128>>>((float*)p_x, ln2s, ln2b, (__half*)p_y);

    // launch 9: MLP1 (bias + gelu -> fp16)
    gemm_h<EPI_GELU_H><<<dim3(16, 128), 128, GM_DSMEM>>>(
        (__half*)p_y, (__half*)p_w1t, p_h,
        NTOK, MLPD, D_, b1, nullptr);

    // launch 10: MLP2 (+bias +residual -> fp32 out)
    gemm_h<EPI_ADDBIAS_F><<<dim3(4, 128), 128, GM_DSMEM>>>(
        (__half*)p_h, (__half*)p_w2t, out,
        NTOK, D_, MLPD, b2, (float*)p_x);
}

// round 7
// speedup vs baseline: 2.8599x; 1.3286x over previous
#include <cuda_runtime.h>
#include <cuda_fp16.h>

// ---------------------------------------------------------------------------
// LocalTransformerBlock, fp16 mma.sync (m16n8k16, fp32 accum) GEMMs.
// R6 resubmit (infra failure last round): ldmatrix.x4 fragment loads +
// 256-thread CTAs (8 warps, 64x32 warp tile).
// B=4, L=4096, D=512, H=8, DH=64, MLP=2048, BS=128
// ---------------------------------------------------------------------------

#define NTOK 16384
#define D_   512
#define DH_  64
#define QKVN 1536
#define MLPD 2048
#define BS_  128

// ---- device scratch ----
__device__ __half g_xin[NTOK * D_];
__device__ __half g_qkv[NTOK * QKVN];
__device__ __half g_ctx[NTOK * D_];
__device__ float  g_x[NTOK * D_];
__device__ __half g_y[NTOK * D_];
__device__ __half g_h[NTOK * MLPD];
__device__ __half g_wqkv[QKVN * D_];   // [N][K] transposed
__device__ __half g_wot[D_ * D_];
__device__ __half g_w1t[MLPD * D_];
__device__ __half g_w2t[D_ * MLPD];

// ---- helpers ----
__device__ __forceinline__ float rnd_tf32(float x) {
    unsigned u;
    asm("cvt.rna.tf32.f32 %0, %1;" : "=r"(u) : "f"(x));
    return __uint_as_float(u);
}
__device__ __forceinline__ float gelu_tanh(float x) {
    float a = 0.7978845608028654f * (x + 0.044715f * x * x * x);
    float t;
    asm("tanh.approx.f32 %0, %1;" : "=f"(t) : "f"(a));
    return 0.5f * x * (1.0f + t);
}
__device__ __forceinline__ void cp16(unsigned dst, const void* src) {
    asm volatile("cp.async.cg.shared.global [%0], [%1], 16;\n" :: "r"(dst), "l"(src));
}
#define CP_COMMIT asm volatile("cp.async.commit_group;\n")
#define CP_WAIT0  asm volatile("cp.async.wait_group 0;\n")

#define LDSM4(r0, r1, r2, r3, addr)                                            \
    asm volatile("ldmatrix.sync.aligned.m8n8.x4.shared.b16 {%0,%1,%2,%3}, [%4];" \
        : "=r"(r0), "=r"(r1), "=r"(r2), "=r"(r3) : "r"(addr))

// fp16 mma m16n8k16, fp32 accum
#define MMA16(c, a0, a1, a2, a3, b0, b1)                                       \
    asm volatile(                                                              \
        "mma.sync.aligned.m16n8k16.row.col.f32.f16.f16.f32 "                   \
        "{%0,%1,%2,%3},{%4,%5,%6,%7},{%8,%9},{%0,%1,%2,%3};"                   \
        : "+f"((c)[0]), "+f"((c)[1]), "+f"((c)[2]), "+f"((c)[3])               \
        : "r"(a0), "r"(a1), "r"(a2), "r"(a3), "r"(b0), "r"(b1))

// tf32 mma m16n8k8 (attention)
#define MMA8(c, a0, a1, a2, a3, b0, b1)                                        \
    asm volatile(                                                              \
        "mma.sync.aligned.m16n8k8.row.col.f32.tf32.tf32.f32 "                  \
        "{%0,%1,%2,%3},{%4,%5,%6,%7},{%8,%9},{%0,%1,%2,%3};"                   \
        : "+f"((c)[0]), "+f"((c)[1]), "+f"((c)[2]), "+f"((c)[3])               \
        : "r"(a0), "r"(a1), "r"(a2), "r"(a3), "r"(b0), "r"(b1))

// ---------------------------------------------------------------------------
// Weight prep: transpose + fp16 convert.  dst[n*R + k] = h(src[k*C + n])
// ---------------------------------------------------------------------------
__global__ void __launch_bounds__(256)
transpose_h(const float* __restrict__ src, __half* __restrict__ dst,
            int R, int C) {
    __shared__ float t[32][33];
    const int n0 = blockIdx.x * 32, k0 = blockIdx.y * 32;
    const int x = threadIdx.x, y = threadIdx.y;
#pragma unroll
    for (int i = 0; i < 32; i += 8)
        t[y + i][x] = src[(size_t)(k0 + y + i) * C + n0 + x];
    __syncthreads();
#pragma unroll
    for (int i = 0; i < 32; i += 8)
        dst[(size_t)(n0 + y + i) * R + k0 + x] = __float2half_rn(t[x][y + i]);
}

__global__ void __launch_bounds__(256)
prep_qkv(const float* __restrict__ wq, const float* __restrict__ wk,
         const float* __restrict__ wv, __half* __restrict__ dst) {
    const float* src = blockIdx.z == 0 ? wq : (blockIdx.z == 1 ? wk : wv);
    __half* d = dst + (size_t)blockIdx.z * D_ * D_;
    __shared__ float t[32][33];
    const int n0 = blockIdx.x * 32, k0 = blockIdx.y * 32;
    const int x = threadIdx.x, y = threadIdx.y;
#pragma unroll
    for (int i = 0; i < 32; i += 8)
        t[y + i][x] = src[(size_t)(k0 + y + i) * D_ + n0 + x];
    __syncthreads();
#pragma unroll
    for (int i = 0; i < 32; i += 8)
        d[(size_t)(n0 + y + i) * D_ + k0 + x] = __float2half_rn(t[x][y + i]);
}

// ---------------------------------------------------------------------------
// LayerNorm: fp32 in -> fp16 out. One block per token row, 128 threads.
// ---------------------------------------------------------------------------
__global__ void __launch_bounds__(128)
ln_kernel(const float* __restrict__ in, const float* __restrict__ scale,
          const float* __restrict__ bias, __half* __restrict__ out) {
    const int row = blockIdx.x;
    const int tid = threadIdx.x;
    float4 v = reinterpret_cast<const float4*>(in + (size_t)row * D_)[tid];
    float s  = v.x + v.y + v.z + v.w;
    float s2 = v.x * v.x + v.y * v.y + v.z * v.z + v.w * v.w;
#pragma unroll
    for (int o = 16; o > 0; o >>= 1) {
        s  += __shfl_xor_sync(0xffffffffu, s, o);
        s2 += __shfl_xor_sync(0xffffffffu, s2, o);
    }
    __shared__ float rs[4], rq[4];
    if ((tid & 31) == 0) { rs[tid >> 5] = s; rq[tid >> 5] = s2; }
    __syncthreads();
    s  = rs[0] + rs[1] + rs[2] + rs[3];
    s2 = rq[0] + rq[1] + rq[2] + rq[3];
    const float mu  = s * (1.0f / D_);
    const float var = s2 * (1.0f / D_) - mu * mu;
    const float inv = rsqrtf(var + 1e-6f);
    float4 sc = reinterpret_cast<const float4*>(scale)[tid];
    float4 bi = reinterpret_cast<const float4*>(bias)[tid];
    __half2 h0 = __floats2half2_rn((v.x - mu) * inv * sc.x + bi.x,
                                   (v.y - mu) * inv * sc.y + bi.y);
    __half2 h1 = __floats2half2_rn((v.z - mu) * inv * sc.z + bi.z,
                                   (v.w - mu) * inv * sc.w + bi.w);
    __half2* op = reinterpret_cast<__half2*>(out + (size_t)row * D_) + tid * 2;
    op[0] = h0; op[1] = h1;
}

// ---------------------------------------------------------------------------
// fp16 GEMM: C[M,N] = A[M,K] (row-major fp16) * Bt[N,K] (K-major fp16),
// fp32 accumulate. BM=128, BN=128, BK=64, 256 threads (8 warps 2x4,
// warp tile 64x32). Double-buffered cp.async, XOR-swizzled smem, ldmatrix.
// ---------------------------------------------------------------------------
constexpr int EPI_H = 0;        // C fp16 = acc                    (qkv)
constexpr int EPI_ADD_F = 1;    // C fp32 = acc + add              (o-proj)
constexpr int EPI_GELU_H = 2;   // C fp16 = gelu(acc + bias)       (mlp1)
constexpr int EPI_ADDBIAS_F = 3;// C fp32 = acc + bias + add       (mlp2)

constexpr int STAGE = 32768;                 // 16KB A + 16KB B
constexpr int GM_DSMEM = 2 * STAGE + 1024;

template <int EPI>
__global__ void __launch_bounds__(256)
gemm_h(const __half* __restrict__ A, const __half* __restrict__ Bt,
       void* __restrict__ Cv, int M, int N, int K,
       const float* __restrict__ bias, const float* __restrict__ add) {
    extern __shared__ float dyn[];
    char* smf = (char*)(((size_t)(char*)dyn + 1023) & ~(size_t)1023);
    const unsigned sbase = (unsigned)__cvta_generic_to_shared(smf);

    const int tid = threadIdx.x, lane = tid & 31, w = tid >> 5;
    const int g = lane >> 2, q = lane & 3;
    const int wm = (w >> 2) * 64, wn = (w & 3) * 32;
    const int bm = blockIdx.y * 128, bn = blockIdx.x * 128;
    const int KT = K >> 6;

    // ldmatrix per-lane row/chunk geometry (constant across ks/kt)
    // A x4: lanes 0-15 -> rows m0+(lane&15) @ chunk lo; 16-31 -> same rows @ hi
    const int a_row = lane & 15;            // + wm + mt*16
    const int a_hi  = lane >> 4;            // chunk offset 0/1
    // B x4: lanes 0-7 n0..7@lo, 8-15 n0..7@hi, 16-23 n8..15@lo, 24-31 n8..15@hi
    const int b_row = (lane & 7) + ((lane >> 4) << 3);  // + wn + bt*16
    const int b_hi  = (lane >> 3) & 1;

    float acc[4][4][4];
#pragma unroll
    for (int mt = 0; mt < 4; mt++)
#pragma unroll
        for (int nt = 0; nt < 4; nt++)
#pragma unroll
            for (int l = 0; l < 4; l++) acc[mt][nt][l] = 0.0f;

    auto load_stage = [&](int s, int kt) {
        const unsigned ua = sbase + s * STAGE;
        const unsigned ub = ua + 16384;
        const __half* Ag = A + (size_t)bm * K + kt * 64;
        const __half* Bg = Bt + (size_t)bn * K + kt * 64;
#pragma unroll
        for (int t = 0; t < 4; t++) {
            const int idx = tid + t * 256;
            const int r = idx >> 3, c = idx & 7;
            cp16(ua + r * 128 + ((c ^ (r & 7)) << 4), Ag + (size_t)r * K + c * 8);
        }
#pragma unroll
        for (int t = 0; t < 4; t++) {
            const int idx = tid + t * 256;
            const int r = idx >> 3, c = idx & 7;
            cp16(ub + r * 128 + ((c ^ (r & 7)) << 4), Bg + (size_t)r * K + c * 8);
        }
        CP_COMMIT;
    };

    load_stage(0, 0);

    for (int kt = 0; kt < KT; kt++) {
        CP_WAIT0;
        __syncthreads();
        if (kt + 1 < KT) load_stage((kt + 1) & 1, kt + 1);

        const unsigned uA = sbase + (kt & 1) * STAGE;
        const unsigned uB = uA + 16384;
#pragma unroll
        for (int ks = 0; ks < 4; ks++) {
            const int ch0 = 2 * ks;
            unsigned af[4][4];
#pragma unroll
            for (int mt = 0; mt < 4; mt++) {
                const int r = wm + mt * 16 + a_row;
                const unsigned addr =
                    uA + r * 128 + (((ch0 + a_hi) ^ (r & 7)) << 4);
                LDSM4(af[mt][0], af[mt][1], af[mt][2], af[mt][3], addr);
            }
#pragma unroll
            for (int bt = 0; bt < 2; bt++) {
                const int nr = wn + bt * 16 + b_row;
                const unsigned addr =
                    uB + nr * 128 + (((ch0 + b_hi) ^ (nr & 7)) << 4);
                unsigned b0, b1, b2, b3;
                LDSM4(b0, b1, b2, b3, addr);
#pragma unroll
                for (int mt = 0; mt < 4; mt++) {
                    MMA16(acc[mt][bt * 2 + 0], af[mt][0], af[mt][1],
                          af[mt][2], af[mt][3], b0, b1);
                    MMA16(acc[mt][bt * 2 + 1], af[mt][0], af[mt][1],
                          af[mt][2], af[mt][3], b2, b3);
                }
            }
        }
    }

    // ---- epilogue ----
#pragma unroll
    for (int mt = 0; mt < 4; mt++) {
#pragma unroll
        for (int nt = 0; nt < 4; nt++) {
            const int r0 = bm + wm + mt * 16 + g;
            const int c0 = bn + wn + nt * 8 + 2 * q;
            float bx = 0.0f, by = 0.0f;
            if (EPI == EPI_GELU_H || EPI == EPI_ADDBIAS_F) {
                float2 bv = *reinterpret_cast<const float2*>(bias + c0);
                bx = bv.x; by = bv.y;
            }
#pragma unroll
            for (int hf = 0; hf < 2; hf++) {
                const int r = r0 + hf * 8;
                float v0 = acc[mt][nt][hf * 2 + 0] + bx;
                float v1 = acc[mt][nt][hf * 2 + 1] + by;
                const size_t idx = (size_t)r * N + c0;
                if (EPI == EPI_GELU_H) { v0 = gelu_tanh(v0); v1 = gelu_tanh(v1); }
                if (EPI == EPI_ADD_F || EPI == EPI_ADDBIAS_F) {
                    float2 av = *reinterpret_cast<const float2*>(add + idx);
                    v0 += av.x; v1 += av.y;
                    float2 o; o.x = v0; o.y = v1;
                    *reinterpret_cast<float2*>((float*)Cv + idx) = o;
                } else {
                    *reinterpret_cast<__half2*>((__half*)Cv + idx) =
                        __floats2half2_rn(v0, v1);
                }
            }
        }
    }
}

// ---------------------------------------------------------------------------
// Block-local attention (tf32 mma path, proven). fp16 in/out.
// CTA per (block, head); QKV fused input stride 1536.
// ---------------------------------------------------------------------------
constexpr int ASQ = 68, ASV = 72, ASP = 132;
constexpr int ATT_SMEM_BYTES = (2 * 128 * ASQ + 128 * ASV) * 4;

__global__ void __launch_bounds__(256)
attn_kernel(const __half* __restrict__ QKV, __half* __restrict__ CTX) {
    extern __shared__ float sm[];
    float* Qs = sm;
    float* Ks = sm + 128 * ASQ;
    float* Vs = sm + 2 * 128 * ASQ;
    float* Ps = sm;  // alias over Qs+Ks

    const int tid = threadIdx.x, lane = tid & 31, w = tid >> 5;
    const int g = lane >> 2, q = lane & 3;
    const int blk = blockIdx.x >> 3;
    const int h   = blockIdx.x & 7;
    const int t0  = blk * BS_;
    const int fb  = h * DH_;

#pragma unroll
    for (int t = 0; t < 8; t++) {
        const int idx = tid + t * 256;
        const int r = idx >> 4, c4 = (idx & 15) * 4;
        const size_t rowb = (size_t)(t0 + r) * QKVN;
        const __half2* qp = reinterpret_cast<const __half2*>(QKV + rowb + fb + c4);
        const __half2* kp = reinterpret_cast<const __half2*>(QKV + rowb + 512 + fb + c4);
        const __half2* vp = reinterpret_cast<const __half2*>(QKV + rowb + 1024 + fb + c4);
        float2 q0 = __half22float2(qp[0]), q1 = __half22float2(qp[1]);
        float2 k0 = __half22float2(kp[0]), k1 = __half22float2(kp[1]);
        float2 v0 = __half22float2(vp[0]), v1 = __half22float2(vp[1]);
        float4 qv; qv.x = q0.x * 0.125f; qv.y = q0.y * 0.125f;
        qv.z = q1.x * 0.125f; qv.w = q1.y * 0.125f;
        float4 kv; kv.x = k0.x; kv.y = k0.y; kv.z = k1.x; kv.w = k1.y;
        float4 vv; vv.x = v0.x; vv.y = v0.y; vv.z = v1.x; vv.w = v1.y;
        *reinterpret_cast<float4*>(Qs + r * ASQ + c4) = qv;
        *reinterpret_cast<float4*>(Ks + r * ASQ + c4) = kv;
        *reinterpret_cast<float4*>(Vs + r * ASV + c4) = vv;
    }
    __syncthreads();

    const int mrow = w * 16;
    float sacc[16][4];
#pragma unroll
    for (int nt = 0; nt < 16; nt++)
#pragma unroll
        for (int l = 0; l < 4; l++) sacc[nt][l] = 0.0f;

#pragma unroll
    for (int kt = 0; kt < 8; kt++) {
        const int c = kt * 8 + q;
        const unsigned a0 = __float_as_uint(Qs[(mrow + g) * ASQ + c]);
        const unsigned a1 = __float_as_uint(Qs[(mrow + g + 8) * ASQ + c]);
        const unsigned a2 = __float_as_uint(Qs[(mrow + g) * ASQ + c + 4]);
        const unsigned a3 = __float_as_uint(Qs[(mrow + g + 8) * ASQ + c + 4]);
#pragma unroll
        for (int nt = 0; nt < 16; nt++) {
            const unsigned b0 = __float_as_uint(Ks[(nt * 8 + g) * ASQ + c]);
            const unsigned b1 = __float_as_uint(Ks[(nt * 8 + g) * ASQ + c + 4]);
            MMA8(sacc[nt], a0, a1, a2, a3, b0, b1);
        }
    }
    __syncthreads();

    float m0 = -1e30f, m1 = -1e30f;
#pragma unroll
    for (int nt = 0; nt < 16; nt++) {
        m0 = fmaxf(m0, fmaxf(sacc[nt][0], sacc[nt][1]));
        m1 = fmaxf(m1, fmaxf(sacc[nt][2], sacc[nt][3]));
    }
    m0 = fmaxf(m0, __shfl_xor_sync(0xffffffffu, m0, 1));
    m0 = fmaxf(m0, __shfl_xor_sync(0xffffffffu, m0, 2));
    m1 = fmaxf(m1, __shfl_xor_sync(0xffffffffu, m1, 1));
    m1 = fmaxf(m1, __shfl_xor_sync(0xffffffffu, m1, 2));
    float s0 = 0.0f, s1 = 0.0f;
#pragma unroll
    for (int nt = 0; nt < 16; nt++) {
        sacc[nt][0] = expf(sacc[nt][0] - m0); s0 += sacc[nt][0];
        sacc[nt][1] = expf(sacc[nt][1] - m0); s0 += sacc[nt][1];
        sacc[nt][2] = expf(sacc[nt][2] - m1); s1 += sacc[nt][2];
        sacc[nt][3] = expf(sacc[nt][3] - m1); s1 += sacc[nt][3];
    }
    s0 += __shfl_xor_sync(0xffffffffu, s0, 1);
    s0 += __shfl_xor_sync(0xffffffffu, s0, 2);
    s1 += __shfl_xor_sync(0xffffffffu, s1, 1);
    s1 += __shfl_xor_sync(0xffffffffu, s1, 2);
    const float i0 = 1.0f / s0, i1 = 1.0f / s1;

#pragma unroll
    for (int nt = 0; nt < 16; nt++) {
        const int cc = nt * 8 + 2 * q;
        float2 p0; p0.x = rnd_tf32(sacc[nt][0] * i0);
        p0.y = rnd_tf32(sacc[nt][1] * i0);
        *reinterpret_cast<float2*>(Ps + (mrow + g) * ASP + cc) = p0;
        float2 p1; p1.x = rnd_tf32(sacc[nt][2] * i1);
        p1.y = rnd_tf32(sacc[nt][3] * i1);
        *reinterpret_cast<float2*>(Ps + (mrow + g + 8) * ASP + cc) = p1;
    }
    __syncwarp();

    float o[8][4];
#pragma unroll
    for (int nt = 0; nt < 8; nt++)
#pragma unroll
        for (int l = 0; l < 4; l++) o[nt][l] = 0.0f;
#pragma unroll
    for (int kt = 0; kt < 16; kt++) {
        const int c = kt * 8 + q;
        const unsigned a0 = __float_as_uint(Ps[(mrow + g) * ASP + c]);
        const unsigned a1 = __float_as_uint(Ps[(mrow + g + 8) * ASP + c]);
        const unsigned a2 = __float_as_uint(Ps[(mrow + g) * ASP + c + 4]);
        const unsigned a3 = __float_as_uint(Ps[(mrow + g + 8) * ASP + c + 4]);
#pragma unroll
        for (int nt = 0; nt < 8; nt++) {
            const unsigned b0 = __float_as_uint(Vs[c * ASV + nt * 8 + g]);
            const unsigned b1 = __float_as_uint(Vs[(c + 4) * ASV + nt * 8 + g]);
            MMA8(o[nt], a0, a1, a2, a3, b0, b1);
        }
    }

#pragma unroll
    for (int nt = 0; nt < 8; nt++) {
        const int d0 = nt * 8 + 2 * q;
        const int r = t0 + mrow + g;
        *reinterpret_cast<__half2*>(CTX + (size_t)r * D_ + fb + d0) =
            __floats2half2_rn(o[nt][0], o[nt][1]);
        *reinterpret_cast<__half2*>(CTX + (size_t)(r + 8) * D_ + fb + d0) =
            __floats2half2_rn(o[nt][2], o[nt][3]);
    }
}

// ---------------------------------------------------------------------------
// launch
// ---------------------------------------------------------------------------
extern "C" void kernel_launch(void* const* d_in, const int* in_sizes, int n_in,
                              void* d_out, int out_size) {
    const float* inputs = (const float*)d_in[0];
    const float* ln1s   = (const float*)d_in[1];
    const float* ln1b   = (const float*)d_in[2];
    const float* wq     = (const float*)d_in[3];
    const float* wk     = (const float*)d_in[4];
    const float* wv     = (const float*)d_in[5];
    const float* wo     = (const float*)d_in[6];
    const float* ln2s   = (const float*)d_in[7];
    const float* ln2b   = (const float*)d_in[8];
    const float* w1     = (const float*)d_in[9];
    const float* b1     = (const float*)d_in[10];
    const float* w2     = (const float*)d_in[11];
    const float* b2     = (const float*)d_in[12];
    float* out = (float*)d_out;

    void *p_xin, *p_qkv, *p_ctx, *p_x, *p_y, *p_h;
    void *p_wqkv, *p_wot, *p_w1t, *p_w2t;
    cudaGetSymbolAddress(&p_xin, g_xin);
    cudaGetSymbolAddress(&p_qkv, g_qkv);
    cudaGetSymbolAddress(&p_ctx, g_ctx);
    cudaGetSymbolAddress(&p_x, g_x);
    cudaGetSymbolAddress(&p_y, g_y);
    cudaGetSymbolAddress(&p_h, g_h);
    cudaGetSymbolAddress(&p_wqkv, g_wqkv);
    cudaGetSymbolAddress(&p_wot, g_wot);
    cudaGetSymbolAddress(&p_w1t, g_w1t);
    cudaGetSymbolAddress(&p_w2t, g_w2t);

    cudaFuncSetAttribute(gemm_h<EPI_H>,
        cudaFuncAttributeMaxDynamicSharedMemorySize, GM_DSMEM);
    cudaFuncSetAttribute(gemm_h<EPI_ADD_F>,
        cudaFuncAttributeMaxDynamicSharedMemorySize, GM_DSMEM);
    cudaFuncSetAttribute(gemm_h<EPI_GELU_H>,
        cudaFuncAttributeMaxDynamicSharedMemorySize, GM_DSMEM);
    cudaFuncSetAttribute(gemm_h<EPI_ADDBIAS_F>,
        cudaFuncAttributeMaxDynamicSharedMemorySize, GM_DSMEM);
    cudaFuncSetAttribute(attn_kernel,
        cudaFuncAttributeMaxDynamicSharedMemorySize, ATT_SMEM_BYTES);

    dim3 tb(32, 8);

    // launches 0-3: weight prep (transpose + fp16)
    prep_qkv<<<dim3(16, 16, 3), tb>>>(wq, wk, wv, (__half*)p_wqkv);
    transpose_h<<<dim3(16, 16), tb>>>(wo, (__half*)p_wot, D_, D_);
    transpose_h<<<dim3(64, 16), tb>>>(w1, (__half*)p_w1t, D_, MLPD);
    transpose_h<<<dim3(16, 64), tb>>>(w2, (__half*)p_w2t, MLPD, D_);

    // launch 4: LN1
    ln_kernel<<<NTOK, 128>>>(inputs, ln1s, ln1b, (__half*)p_xin);

    // launch 5: fused QKV GEMM [16384,512] x [1536,512]^T
    gemm_h<EPI_H><<<dim3(12, 128), 256, GM_DSMEM>>>(
        (__half*)p_xin, (__half*)p_wqkv, p_qkv,
        NTOK, QKVN, D_, nullptr, nullptr);

    // launch 6: attention
    attn_kernel<<<1024, 256, ATT_SMEM_BYTES>>>((__half*)p_qkv, (__half*)p_ctx);

    // launch 7: O projection + residual -> x (fp32)
    gemm_h<EPI_ADD_F><<<dim3(4, 128), 256, GM_DSMEM>>>(
        (__half*)p_ctx, (__half*)p_wot, p_x,
        NTOK, D_, D_, nullptr, inputs);

    // launch 8: LN2
    ln_kernel<<<NTOK, 128>>>((float*)p_x, ln2s, ln2b, (__half*)p_y);

    // launch 9: MLP1 (bias + gelu -> fp16)
    gemm_h<EPI_GELU_H><<<dim3(16, 128), 256, GM_DSMEM>>>(
        (__half*)p_y, (__half*)p_w1t, p_h,
        NTOK, MLPD, D_, b1, nullptr);

    // launch 10: MLP2 (+bias +residual -> fp32 out)
    gemm_h<EPI_ADDBIAS_F><<<dim3(4, 128), 256, GM_DSMEM>>>(
        (__half*)p_h, (__half*)p_w2t, out,
        NTOK, D_, MLPD, b2, (float*)p_x);
}

// round 8
// speedup vs baseline: 3.0671x; 1.0725x over previous
#include <cuda_runtime.h>
#include <cuda_fp16.h>

// ---------------------------------------------------------------------------
// LocalTransformerBlock, fp16 mma.sync (m16n8k16, fp32 accum) everywhere.
// R8: attention rewritten to fp16 mma + ldmatrix(+trans) + cp.async loads;
//     4 weight-prep launches merged into one. GEMM identical to R7.
// B=4, L=4096, D=512, H=8, DH=64, MLP=2048, BS=128
// ---------------------------------------------------------------------------

#define NTOK 16384
#define D_   512
#define DH_  64
#define QKVN 1536
#define MLPD 2048
#define BS_  128

// ---- device scratch ----
__device__ __half g_xin[NTOK * D_];
__device__ __half g_qkv[NTOK * QKVN];
__device__ __half g_ctx[NTOK * D_];
__device__ float  g_x[NTOK * D_];
__device__ __half g_y[NTOK * D_];
__device__ __half g_h[NTOK * MLPD];
__device__ __half g_wqkv[QKVN * D_];   // [N][K] transposed
__device__ __half g_wot[D_ * D_];
__device__ __half g_w1t[MLPD * D_];
__device__ __half g_w2t[D_ * MLPD];

// ---- helpers ----
__device__ __forceinline__ float gelu_tanh(float x) {
    float a = 0.7978845608028654f * (x + 0.044715f * x * x * x);
    float t;
    asm("tanh.approx.f32 %0, %1;" : "=f"(t) : "f"(a));
    return 0.5f * x * (1.0f + t);
}
__device__ __forceinline__ void cp16(unsigned dst, const void* src) {
    asm volatile("cp.async.cg.shared.global [%0], [%1], 16;\n" :: "r"(dst), "l"(src));
}
#define CP_COMMIT asm volatile("cp.async.commit_group;\n")
#define CP_WAIT0  asm volatile("cp.async.wait_group 0;\n")

#define LDSM4(r0, r1, r2, r3, addr)                                            \
    asm volatile("ldmatrix.sync.aligned.m8n8.x4.shared.b16 {%0,%1,%2,%3}, [%4];" \
        : "=r"(r0), "=r"(r1), "=r"(r2), "=r"(r3) : "r"(addr))

#define LDSM4T(r0, r1, r2, r3, addr)                                           \
    asm volatile("ldmatrix.sync.aligned.m8n8.x4.trans.shared.b16 {%0,%1,%2,%3}, [%4];" \
        : "=r"(r0), "=r"(r1), "=r"(r2), "=r"(r3) : "r"(addr))

// fp16 mma m16n8k16, fp32 accum
#define MMA16(c, a0, a1, a2, a3, b0, b1)                                       \
    asm volatile(                                                              \
        "mma.sync.aligned.m16n8k16.row.col.f32.f16.f16.f32 "                   \
        "{%0,%1,%2,%3},{%4,%5,%6,%7},{%8,%9},{%0,%1,%2,%3};"                   \
        : "+f"((c)[0]), "+f"((c)[1]), "+f"((c)[2]), "+f"((c)[3])               \
        : "r"(a0), "r"(a1), "r"(a2), "r"(a3), "r"(b0), "r"(b1))

// ---------------------------------------------------------------------------
// Unified weight prep: transpose + fp16 convert, one launch, 3072 tiles.
// dst[n*R + k] = h(src[k*C + n]); tiles are 32x32.
// ---------------------------------------------------------------------------
__global__ void __launch_bounds__(256)
prep_all(const float* __restrict__ wq, const float* __restrict__ wk,
         const float* __restrict__ wv, const float* __restrict__ wo,
         const float* __restrict__ w1, const float* __restrict__ w2,
         __half* __restrict__ dwqkv, __half* __restrict__ dwot,
         __half* __restrict__ dw1t, __half* __restrict__ dw2t) {
    __shared__ float t[32][33];
    const int b = blockIdx.x;
    const float* src; __half* dst; int R, C, n0, k0;
    if (b < 768) {
        const int wsel = b >> 8, r = b & 255;
        src = wsel == 0 ? wq : (wsel == 1 ? wk : wv);
        dst = dwqkv + (size_t)wsel * D_ * D_;
        R = D_; C = D_; n0 = (r & 15) * 32; k0 = (r >> 4) * 32;
    } else if (b < 1024) {
        const int r = b - 768;
        src = wo; dst = dwot;
        R = D_; C = D_; n0 = (r & 15) * 32; k0 = (r >> 4) * 32;
    } else if (b < 2048) {
        const int r = b - 1024;
        src = w1; dst = dw1t;
        R = D_; C = MLPD; n0 = (r & 63) * 32; k0 = (r >> 6) * 32;
    } else {
        const int r = b - 2048;
        src = w2; dst = dw2t;
        R = MLPD; C = D_; n0 = (r & 15) * 32; k0 = (r >> 4) * 32;
    }
    const int x = threadIdx.x, y = threadIdx.y;
#pragma unroll
    for (int i = 0; i < 32; i += 8)
        t[y + i][x] = src[(size_t)(k0 + y + i) * C + n0 + x];
    __syncthreads();
#pragma unroll
    for (int i = 0; i < 32; i += 8)
        dst[(size_t)(n0 + y + i) * R + k0 + x] = __float2half_rn(t[x][y + i]);
}

// ---------------------------------------------------------------------------
// LayerNorm: fp32 in -> fp16 out. One block per token row, 128 threads.
// ---------------------------------------------------------------------------
__global__ void __launch_bounds__(128)
ln_kernel(const float* __restrict__ in, const float* __restrict__ scale,
          const float* __restrict__ bias, __half* __restrict__ out) {
    const int row = blockIdx.x;
    const int tid = threadIdx.x;
    float4 v = reinterpret_cast<const float4*>(in + (size_t)row * D_)[tid];
    float s  = v.x + v.y + v.z + v.w;
    float s2 = v.x * v.x + v.y * v.y + v.z * v.z + v.w * v.w;
#pragma unroll
    for (int o = 16; o > 0; o >>= 1) {
        s  += __shfl_xor_sync(0xffffffffu, s, o);
        s2 += __shfl_xor_sync(0xffffffffu, s2, o);
    }
    __shared__ float rs[4], rq[4];
    if ((tid & 31) == 0) { rs[tid >> 5] = s; rq[tid >> 5] = s2; }
    __syncthreads();
    s  = rs[0] + rs[1] + rs[2] + rs[3];
    s2 = rq[0] + rq[1] + rq[2] + rq[3];
    const float mu  = s * (1.0f / D_);
    const float var = s2 * (1.0f / D_) - mu * mu;
    const float inv = rsqrtf(var + 1e-6f);
    float4 sc = reinterpret_cast<const float4*>(scale)[tid];
    float4 bi = reinterpret_cast<const float4*>(bias)[tid];
    __half2 h0 = __floats2half2_rn((v.x - mu) * inv * sc.x + bi.x,
                                   (v.y - mu) * inv * sc.y + bi.y);
    __half2 h1 = __floats2half2_rn((v.z - mu) * inv * sc.z + bi.z,
                                   (v.w - mu) * inv * sc.w + bi.w);
    __half2* op = reinterpret_cast<__half2*>(out + (size_t)row * D_) + tid * 2;
    op[0] = h0; op[1] = h1;
}

// ---------------------------------------------------------------------------
// fp16 GEMM (identical to R7): C[M,N] = A[M,K] * Bt[N,K], fp32 accum.
// BM=128, BN=128, BK=64, 256 threads (8 warps 2x4, warp tile 64x32),
// double-buffered cp.async, XOR-swizzled smem, ldmatrix.
// ---------------------------------------------------------------------------
constexpr int EPI_H = 0;        // C fp16 = acc                    (qkv)
constexpr int EPI_ADD_F = 1;    // C fp32 = acc + add              (o-proj)
constexpr int EPI_GELU_H = 2;   // C fp16 = gelu(acc + bias)       (mlp1)
constexpr int EPI_ADDBIAS_F = 3;// C fp32 = acc + bias + add       (mlp2)

constexpr int STAGE = 32768;                 // 16KB A + 16KB B
constexpr int GM_DSMEM = 2 * STAGE + 1024;

template <int EPI>
__global__ void __launch_bounds__(256)
gemm_h(const __half* __restrict__ A, const __half* __restrict__ Bt,
       void* __restrict__ Cv, int M, int N, int K,
       const float* __restrict__ bias, const float* __restrict__ add) {
    extern __shared__ float dyn[];
    char* smf = (char*)(((size_t)(char*)dyn + 1023) & ~(size_t)1023);
    const unsigned sbase = (unsigned)__cvta_generic_to_shared(smf);

    const int tid = threadIdx.x, lane = tid & 31, w = tid >> 5;
    const int g = lane >> 2, q = lane & 3;
    const int wm = (w >> 2) * 64, wn = (w & 3) * 32;
    const int bm = blockIdx.y * 128, bn = blockIdx.x * 128;
    const int KT = K >> 6;

    const int a_row = lane & 15;
    const int a_hi  = lane >> 4;
    const int b_row = (lane & 7) + ((lane >> 4) << 3);
    const int b_hi  = (lane >> 3) & 1;

    float acc[4][4][4];
#pragma unroll
    for (int mt = 0; mt < 4; mt++)
#pragma unroll
        for (int nt = 0; nt < 4; nt++)
#pragma unroll
            for (int l = 0; l < 4; l++) acc[mt][nt][l] = 0.0f;

    auto load_stage = [&](int s, int kt) {
        const unsigned ua = sbase + s * STAGE;
        const unsigned ub = ua + 16384;
        const __half* Ag = A + (size_t)bm * K + kt * 64;
        const __half* Bg = Bt + (size_t)bn * K + kt * 64;
#pragma unroll
        for (int t = 0; t < 4; t++) {
            const int idx = tid + t * 256;
            const int r = idx >> 3, c = idx & 7;
            cp16(ua + r * 128 + ((c ^ (r & 7)) << 4), Ag + (size_t)r * K + c * 8);
        }
#pragma unroll
        for (int t = 0; t < 4; t++) {
            const int idx = tid + t * 256;
            const int r = idx >> 3, c = idx & 7;
            cp16(ub + r * 128 + ((c ^ (r & 7)) << 4), Bg + (size_t)r * K + c * 8);
        }
        CP_COMMIT;
    };

    load_stage(0, 0);

    for (int kt = 0; kt < KT; kt++) {
        CP_WAIT0;
        __syncthreads();
        if (kt + 1 < KT) load_stage((kt + 1) & 1, kt + 1);

        const unsigned uA = sbase + (kt & 1) * STAGE;
        const unsigned uB = uA + 16384;
#pragma unroll
        for (int ks = 0; ks < 4; ks++) {
            const int ch0 = 2 * ks;
            unsigned af[4][4];
#pragma unroll
            for (int mt = 0; mt < 4; mt++) {
                const int r = wm + mt * 16 + a_row;
                const unsigned addr =
                    uA + r * 128 + (((ch0 + a_hi) ^ (r & 7)) << 4);
                LDSM4(af[mt][0], af[mt][1], af[mt][2], af[mt][3], addr);
            }
#pragma unroll
            for (int bt = 0; bt < 2; bt++) {
                const int nr = wn + bt * 16 + b_row;
                const unsigned addr =
                    uB + nr * 128 + (((ch0 + b_hi) ^ (nr & 7)) << 4);
                unsigned b0, b1, b2, b3;
                LDSM4(b0, b1, b2, b3, addr);
#pragma unroll
                for (int mt = 0; mt < 4; mt++) {
                    MMA16(acc[mt][bt * 2 + 0], af[mt][0], af[mt][1],
                          af[mt][2], af[mt][3], b0, b1);
                    MMA16(acc[mt][bt * 2 + 1], af[mt][0], af[mt][1],
                          af[mt][2], af[mt][3], b2, b3);
                }
            }
        }
    }

    // ---- epilogue ----
#pragma unroll
    for (int mt = 0; mt < 4; mt++) {
#pragma unroll
        for (int nt = 0; nt < 4; nt++) {
            const int r0 = bm + wm + mt * 16 + g;
            const int c0 = bn + wn + nt * 8 + 2 * q;
            float bx = 0.0f, by = 0.0f;
            if (EPI == EPI_GELU_H || EPI == EPI_ADDBIAS_F) {
                float2 bv = *reinterpret_cast<const float2*>(bias + c0);
                bx = bv.x; by = bv.y;
            }
#pragma unroll
            for (int hf = 0; hf < 2; hf++) {
                const int r = r0 + hf * 8;
                float v0 = acc[mt][nt][hf * 2 + 0] + bx;
                float v1 = acc[mt][nt][hf * 2 + 1] + by;
                const size_t idx = (size_t)r * N + c0;
                if (EPI == EPI_GELU_H) { v0 = gelu_tanh(v0); v1 = gelu_tanh(v1); }
                if (EPI == EPI_ADD_F || EPI == EPI_ADDBIAS_F) {
                    float2 av = *reinterpret_cast<const float2*>(add + idx);
                    v0 += av.x; v1 += av.y;
                    float2 o; o.x = v0; o.y = v1;
                    *reinterpret_cast<float2*>((float*)Cv + idx) = o;
                } else {
                    *reinterpret_cast<__half2*>((__half*)Cv + idx) =
                        __floats2half2_rn(v0, v1);
                }
            }
        }
    }
}

// ---------------------------------------------------------------------------
// Block-local attention, fp16 mma + ldmatrix. CTA per (block, head).
// smem: Qh 16KB @0, Kh 16KB @16384, Vh 16KB @32768; Ph 32KB aliased @0.
// All rows 128B (64 fp16) XOR-swizzled; Ph rows 256B (128 fp16).
// ---------------------------------------------------------------------------
constexpr int ATT_SMEM_BYTES = 49152 + 1024;

__global__ void __launch_bounds__(256)
attn_kernel(const __half* __restrict__ QKV, __half* __restrict__ CTX) {
    extern __shared__ char smem_raw[];
    char* smp = (char*)(((size_t)smem_raw + 1023) & ~(size_t)1023);
    const unsigned sb = (unsigned)__cvta_generic_to_shared(smp);
    const unsigned uQ = sb, uK = sb + 16384, uV = sb + 32768, uP = sb;

    const int tid = threadIdx.x, lane = tid & 31, w = tid >> 5;
    const int g = lane >> 2, q = lane & 3;
    const int blk = blockIdx.x >> 3;
    const int h   = blockIdx.x & 7;
    const int t0  = blk * BS_;
    const int fb  = h * DH_;

    // bulk load Q,K,V: 128 rows x 8 chunks(16B) each, cp.async
#pragma unroll
    for (int t = 0; t < 4; t++) {
        const int idx = tid + t * 256;        // 0..1023
        const int r = idx >> 3, c = idx & 7;
        const __half* gl = QKV + (size_t)(t0 + r) * QKVN + fb + c * 8;
        const unsigned off = r * 128 + ((c ^ (r & 7)) << 4);
        cp16(uQ + off, gl);
        cp16(uK + off, gl + 512);
        cp16(uV + off, gl + 1024);
    }
    CP_COMMIT;
    CP_WAIT0;
    __syncthreads();

    const int mrow = w * 16;
    const int a_row = lane & 15, a_hi = lane >> 4;
    const int b_row = (lane & 7) + ((lane >> 4) << 3), b_hi = (lane >> 3) & 1;

    // ---- S = Q K^T : warp tile 16x128, K-dim 64 (4 k16 steps) ----
    float sacc[16][4];
#pragma unroll
    for (int nt = 0; nt < 16; nt++)
#pragma unroll
        for (int l = 0; l < 4; l++) sacc[nt][l] = 0.0f;

#pragma unroll
    for (int ks = 0; ks < 4; ks++) {
        const int ch0 = 2 * ks;
        unsigned a0, a1, a2, a3;
        {
            const int r = mrow + a_row;
            LDSM4(a0, a1, a2, a3, uQ + r * 128 + (((ch0 + a_hi) ^ (r & 7)) << 4));
        }
#pragma unroll
        for (int bt = 0; bt < 8; bt++) {
            const int nr = bt * 16 + b_row;
            unsigned b0, b1, b2, b3;
            LDSM4(b0, b1, b2, b3, uK + nr * 128 + (((ch0 + b_hi) ^ (nr & 7)) << 4));
            MMA16(sacc[bt * 2 + 0], a0, a1, a2, a3, b0, b1);
            MMA16(sacc[bt * 2 + 1], a0, a1, a2, a3, b2, b3);
        }
    }
    __syncthreads();   // all warps done reading Q/K before Ph overwrites them

    // ---- softmax over 128 cols (apply DH^-1/2 = 0.125 here) ----
    float m0 = -1e30f, m1 = -1e30f;
#pragma unroll
    for (int nt = 0; nt < 16; nt++) {
        sacc[nt][0] *= 0.125f; sacc[nt][1] *= 0.125f;
        sacc[nt][2] *= 0.125f; sacc[nt][3] *= 0.125f;
        m0 = fmaxf(m0, fmaxf(sacc[nt][0], sacc[nt][1]));
        m1 = fmaxf(m1, fmaxf(sacc[nt][2], sacc[nt][3]));
    }
    m0 = fmaxf(m0, __shfl_xor_sync(0xffffffffu, m0, 1));
    m0 = fmaxf(m0, __shfl_xor_sync(0xffffffffu, m0, 2));
    m1 = fmaxf(m1, __shfl_xor_sync(0xffffffffu, m1, 1));
    m1 = fmaxf(m1, __shfl_xor_sync(0xffffffffu, m1, 2));
    float s0 = 0.0f, s1 = 0.0f;
#pragma unroll
    for (int nt = 0; nt < 16; nt++) {
        sacc[nt][0] = expf(sacc[nt][0] - m0); s0 += sacc[nt][0];
        sacc[nt][1] = expf(sacc[nt][1] - m0); s0 += sacc[nt][1];
        sacc[nt][2] = expf(sacc[nt][2] - m1); s1 += sacc[nt][2];
        sacc[nt][3] = expf(sacc[nt][3] - m1); s1 += sacc[nt][3];
    }
    s0 += __shfl_xor_sync(0xffffffffu, s0, 1);
    s0 += __shfl_xor_sync(0xffffffffu, s0, 2);
    s1 += __shfl_xor_sync(0xffffffffu, s1, 1);
    s1 += __shfl_xor_sync(0xffffffffu, s1, 2);
    const float i0 = 1.0f / s0, i1 = 1.0f / s1;

    // ---- write P (fp16) to smem: rows 256B, 16 chunks, XOR-swizzled ----
    {
        char* pp = smp;
#pragma unroll
        for (int nt = 0; nt < 16; nt++) {
            const int r0 = mrow + g, r1 = mrow + g + 8;
            const unsigned o0 = r0 * 256 + ((nt ^ (r0 & 7)) << 4) + 4 * q;
            const unsigned o1 = r1 * 256 + ((nt ^ (r1 & 7)) << 4) + 4 * q;
            *reinterpret_cast<__half2*>(pp + o0) =
                __floats2half2_rn(sacc[nt][0] * i0, sacc[nt][1] * i0);
            *reinterpret_cast<__half2*>(pp + o1) =
                __floats2half2_rn(sacc[nt][2] * i1, sacc[nt][3] * i1);
        }
    }
    __syncwarp();   // each warp consumes only its own 16 P rows

    // ---- ctx = P V : K-dim 128 (8 k16 steps), N=64 ----
    float o[8][4];
#pragma unroll
    for (int nt = 0; nt < 8; nt++)
#pragma unroll
        for (int l = 0; l < 4; l++) o[nt][l] = 0.0f;

    const int vi  = lane >> 3;                      // matrix index 0..3
    const int vrk = ((vi & 1) << 3) + (lane & 7);   // k row within 16
    const int vch = vi >> 1;                        // n-chunk offset 0/1
#pragma unroll
    for (int ks = 0; ks < 8; ks++) {
        unsigned a0, a1, a2, a3;
        {
            const int r = mrow + a_row;
            LDSM4(a0, a1, a2, a3,
                  uP + r * 256 + (((2 * ks + a_hi) ^ (r & 7)) << 4));
        }
#pragma unroll
        for (int vt = 0; vt < 4; vt++) {   // 16 d-cols per vt
            const int rk = ks * 16 + vrk;
            const int ch = vt * 2 + vch;
            unsigned b0, b1, b2, b3;
            LDSM4T(b0, b1, b2, b3, uV + rk * 128 + ((ch ^ (rk & 7)) << 4));
            MMA16(o[vt * 2 + 0], a0, a1, a2, a3, b0, b1);
            MMA16(o[vt * 2 + 1], a0, a1, a2, a3, b2, b3);
        }
    }

    // ---- write ctx (fp16) ----
#pragma unroll
    for (int nt = 0; nt < 8; nt++) {
        const int d0 = nt * 8 + 2 * q;
        const int r = t0 + mrow + g;
        *reinterpret_cast<__half2*>(CTX + (size_t)r * D_ + fb + d0) =
            __floats2half2_rn(o[nt][0], o[nt][1]);
        *reinterpret_cast<__half2*>(CTX + (size_t)(r + 8) * D_ + fb + d0) =
            __floats2half2_rn(o[nt][2], o[nt][3]);
    }
}

// ---------------------------------------------------------------------------
// launch
// ---------------------------------------------------------------------------
extern "C" void kernel_launch(void* const* d_in, const int* in_sizes, int n_in,
                              void* d_out, int out_size) {
    const float* inputs = (const float*)d_in[0];
    const float* ln1s   = (const float*)d_in[1];
    const float* ln1b   = (const float*)d_in[2];
    const float* wq     = (const float*)d_in[3];
    const float* wk     = (const float*)d_in[4];
    const float* wv     = (const float*)d_in[5];
    const float* wo     = (const float*)d_in[6];
    const float* ln2s   = (const float*)d_in[7];
    const float* ln2b   = (const float*)d_in[8];
    const float* w1     = (const float*)d_in[9];
    const float* b1     = (const float*)d_in[10];
    const float* w2     = (const float*)d_in[11];
    const float* b2     = (const float*)d_in[12];
    float* out = (float*)d_out;

    void *p_xin, *p_qkv, *p_ctx, *p_x, *p_y, *p_h;
    void *p_wqkv, *p_wot, *p_w1t, *p_w2t;
    cudaGetSymbolAddress(&p_xin, g_xin);
    cudaGetSymbolAddress(&p_qkv, g_qkv);
    cudaGetSymbolAddress(&p_ctx, g_ctx);
    cudaGetSymbolAddress(&p_x, g_x);
    cudaGetSymbolAddress(&p_y, g_y);
    cudaGetSymbolAddress(&p_h, g_h);
    cudaGetSymbolAddress(&p_wqkv, g_wqkv);
    cudaGetSymbolAddress(&p_wot, g_wot);
    cudaGetSymbolAddress(&p_w1t, g_w1t);
    cudaGetSymbolAddress(&p_w2t, g_w2t);

    cudaFuncSetAttribute(gemm_h<EPI_H>,
        cudaFuncAttributeMaxDynamicSharedMemorySize, GM_DSMEM);
    cudaFuncSetAttribute(gemm_h<EPI_ADD_F>,
        cudaFuncAttributeMaxDynamicSharedMemorySize, GM_DSMEM);
    cudaFuncSetAttribute(gemm_h<EPI_GELU_H>,
        cudaFuncAttributeMaxDynamicSharedMemorySize, GM_DSMEM);
    cudaFuncSetAttribute(gemm_h<EPI_ADDBIAS_F>,
        cudaFuncAttributeMaxDynamicSharedMemorySize, GM_DSMEM);
    cudaFuncSetAttribute(attn_kernel,
        cudaFuncAttributeMaxDynamicSharedMemorySize, ATT_SMEM_BYTES);

    // launch 0: unified weight prep
    prep_all<<<3072, dim3(32, 8)>>>(wq, wk, wv, wo, w1, w2,
        (__half*)p_wqkv, (__half*)p_wot, (__half*)p_w1t, (__half*)p_w2t);

    // launch 1: LN1
    ln_kernel<<<NTOK, 128>>>(inputs, ln1s, ln1b, (__half*)p_xin);

    // launch 2: fused QKV GEMM [16384,512] x [1536,512]^T
    gemm_h<EPI_H><<<dim3(12, 128), 256, GM_DSMEM>>>(
        (__half*)p_xin, (__half*)p_wqkv, p_qkv,
        NTOK, QKVN, D_, nullptr, nullptr);

    // launch 3: attention
    attn_kernel<<<1024, 256, ATT_SMEM_BYTES>>>((__half*)p_qkv, (__half*)p_ctx);

    // launch 4: O projection + residual -> x (fp32)
    gemm_h<EPI_ADD_F><<<dim3(4, 128), 256, GM_DSMEM>>>(
        (__half*)p_ctx, (__half*)p_wot, p_x,
        NTOK, D_, D_, nullptr, inputs);

    // launch 5: LN2
    ln_kernel<<<NTOK, 128>>>((float*)p_x, ln2s, ln2b, (__half*)p_y);

    // launch 6: MLP1 (bias + gelu -> fp16)
    gemm_h<EPI_GELU_H><<<dim3(16, 128), 256, GM_DSMEM>>>(
        (__half*)p_y, (__half*)p_w1t, p_h,
        NTOK, MLPD, D_, b1, nullptr);

    // launch 7: MLP2 (+bias +residual -> fp32 out)
    gemm_h<EPI_ADDBIAS_F><<<dim3(4, 128), 256, GM_DSMEM>>>(
        (__half*)p_h, (__half*)p_w2t, out,
        NTOK, D_, MLPD, b2, (float*)p_x);
}